// round 1
// baseline (speedup 1.0000x reference)
#include <cuda_runtime.h>
#include <cuda_bf16.h>
#include <cstdint>

#define N_NODES 100000
#define N_EDGES 1600000
#define D 128
#define K2 256   // 2*D

// Scratch (no device mallocs allowed)
__device__ float g_sum[(size_t)N_NODES * D];   // 51.2 MB
__device__ int   g_deg[N_NODES];
__device__ float g_Wt[K2 * D];                 // W transposed: Wt[k][n] = W[n][k]

// ---------------------------------------------------------------------------
// Transpose W [128 out][256 in] -> Wt [256 k][128 n]
// ---------------------------------------------------------------------------
__global__ void transpose_W(const float* __restrict__ W) {
    int k = blockIdx.x;      // 0..255
    int n = threadIdx.x;     // 0..127
    g_Wt[k * D + n] = W[n * K2 + k];
}

// ---------------------------------------------------------------------------
// Scatter: one warp per edge, vector float4 atomics into g_sum, deg count.
// ---------------------------------------------------------------------------
__global__ void scatter_edges(const float* __restrict__ h,
                              const int* __restrict__ esrc,
                              const int* __restrict__ edst) {
    int gtid   = blockIdx.x * blockDim.x + threadIdx.x;
    int warp   = gtid >> 5;
    int lane   = threadIdx.x & 31;
    int nwarps = (gridDim.x * blockDim.x) >> 5;

    for (int e = warp; e < N_EDGES; e += nwarps) {
        int s = esrc[e];
        int d = edst[e];
        float4 v = *(const float4*)(h + (size_t)s * D + lane * 4);
        float* p = g_sum + (size_t)d * D + lane * 4;
        asm volatile("red.global.add.v4.f32 [%0], {%1,%2,%3,%4};"
                     :: "l"(p), "f"(v.x), "f"(v.y), "f"(v.z), "f"(v.w)
                     : "memory");
        if (lane == 0) atomicAdd(&g_deg[d], 1);
    }
}

// ---------------------------------------------------------------------------
// Fused GEMM (M=100000, N=128, K=256) + bias + L2 normalize + ReLU.
// Tile: 64 rows x 128 cols x 16 k. 256 threads, 4x8 micro-tile per thread.
// x[m][k] = h[m][k] for k<128, g_sum[m][k-128] * invdeg[m] for k>=128.
// ---------------------------------------------------------------------------
__global__ void __launch_bounds__(256, 4)
fused_gemm_norm_relu(const float* __restrict__ h,
                     const float* __restrict__ bias,
                     float* __restrict__ out) {
    __shared__ float xs[16][68];       // [k][m], padded (68 keeps 16B align)
    __shared__ float ws[16 * D];       // [k][n]
    __shared__ float invdeg[64];
    __shared__ float ssq[64][17];
    __shared__ float scale_s[64];

    const int tid = threadIdx.x;
    const int tx  = tid & 15;          // col group: n = tx*8..tx*8+7
    const int ty  = tid >> 4;          // row group: m = ty*4..ty*4+3
    const int m0  = blockIdx.x * 64;

    if (tid < 64) {
        int mg = m0 + tid;
        int dg = (mg < N_NODES) ? g_deg[mg] : 1;
        invdeg[tid] = 1.0f / (float)max(dg, 1);
    }
    __syncthreads();

    float acc[4][8];
#pragma unroll
    for (int i = 0; i < 4; i++)
#pragma unroll
        for (int j = 0; j < 8; j++) acc[i][j] = 0.0f;

    // x-tile loader mapping: each thread loads one float4 of one row
    const int ml = tid >> 2;                 // 0..63
    const int kq = (tid & 3) << 2;           // 0,4,8,12
    int mg = m0 + ml;
    if (mg >= N_NODES) mg = N_NODES - 1;     // clamp (results discarded)
    const float idg = invdeg[ml];

    for (int kk = 0; kk < K2; kk += 16) {
        // ---- load x tile (transposed into xs[k][m]) ----
        float4 v;
        if (kk < D) {
            v = *(const float4*)(h + (size_t)mg * D + kk + kq);
        } else {
            float4 s = *(const float4*)(g_sum + (size_t)mg * D + (kk - D) + kq);
            v = make_float4(s.x * idg, s.y * idg, s.z * idg, s.w * idg);
        }
        xs[kq + 0][ml] = v.x;
        xs[kq + 1][ml] = v.y;
        xs[kq + 2][ml] = v.z;
        xs[kq + 3][ml] = v.w;

        // ---- load W tile: 2 float4 per thread, coalesced from g_Wt ----
#pragma unroll
        for (int i = 0; i < 2; i++) {
            int f  = tid * 2 + i;            // 0..511 (float4 index)
            int kl = f >> 5;                 // 0..15
            int nn = (f & 31) << 2;          // 0..124
            *(float4*)&ws[kl * D + nn] =
                *(const float4*)(g_Wt + (size_t)(kk + kl) * D + nn);
        }
        __syncthreads();

        // ---- compute ----
#pragma unroll
        for (int k = 0; k < 16; k++) {
            float4 a  = *(float4*)&xs[k][ty * 4];
            float4 b0 = *(float4*)&ws[k * D + tx * 8];
            float4 b1 = *(float4*)&ws[k * D + tx * 8 + 4];
            float av[4] = {a.x, a.y, a.z, a.w};
            float bv[8] = {b0.x, b0.y, b0.z, b0.w, b1.x, b1.y, b1.z, b1.w};
#pragma unroll
            for (int i = 0; i < 4; i++)
#pragma unroll
                for (int j = 0; j < 8; j++)
                    acc[i][j] += av[i] * bv[j];
        }
        __syncthreads();
    }

    // ---- epilogue: bias, row sum-of-squares, normalize, relu, store ----
    float bb[8];
    *(float4*)&bb[0] = *(const float4*)(bias + tx * 8);
    *(float4*)&bb[4] = *(const float4*)(bias + tx * 8 + 4);

#pragma unroll
    for (int i = 0; i < 4; i++) {
        float s = 0.0f;
#pragma unroll
        for (int j = 0; j < 8; j++) {
            float v = acc[i][j] + bb[j];
            acc[i][j] = v;
            s += v * v;
        }
        ssq[ty * 4 + i][tx] = s;
    }
    __syncthreads();

    if (tid < 64) {
        float s = 0.0f;
#pragma unroll
        for (int j = 0; j < 16; j++) s += ssq[tid][j];
        float nrm = sqrtf(s);
        scale_s[tid] = 1.0f / fmaxf(nrm, 1e-12f);
    }
    __syncthreads();

#pragma unroll
    for (int i = 0; i < 4; i++) {
        int m   = ty * 4 + i;
        int mgl = m0 + m;
        if (mgl < N_NODES) {
            float sc = scale_s[m];
            float4 o0, o1;
            o0.x = fmaxf(acc[i][0] * sc, 0.0f);
            o0.y = fmaxf(acc[i][1] * sc, 0.0f);
            o0.z = fmaxf(acc[i][2] * sc, 0.0f);
            o0.w = fmaxf(acc[i][3] * sc, 0.0f);
            o1.x = fmaxf(acc[i][4] * sc, 0.0f);
            o1.y = fmaxf(acc[i][5] * sc, 0.0f);
            o1.z = fmaxf(acc[i][6] * sc, 0.0f);
            o1.w = fmaxf(acc[i][7] * sc, 0.0f);
            *(float4*)(out + (size_t)mgl * D + tx * 8)     = o0;
            *(float4*)(out + (size_t)mgl * D + tx * 8 + 4) = o1;
        }
    }
}

// ---------------------------------------------------------------------------
extern "C" void kernel_launch(void* const* d_in, const int* in_sizes, int n_in,
                              void* d_out, int out_size) {
    const float* h    = (const float*)d_in[0];
    const float* W    = (const float*)d_in[1];
    const float* bias = (const float*)d_in[2];
    const int*   esrc = (const int*)d_in[3];
    const int*   edst = (const int*)d_in[4];
    float*       out  = (float*)d_out;

    void *p_sum = nullptr, *p_deg = nullptr;
    cudaGetSymbolAddress(&p_sum, g_sum);
    cudaGetSymbolAddress(&p_deg, g_deg);

    cudaMemsetAsync(p_sum, 0, sizeof(float) * (size_t)N_NODES * D, 0);
    cudaMemsetAsync(p_deg, 0, sizeof(int) * N_NODES, 0);

    transpose_W<<<K2, D>>>(W);
    scatter_edges<<<2368, 256>>>(h, esrc, edst);
    fused_gemm_norm_relu<<<(N_NODES + 63) / 64, 256>>>(h, bias, out);
}

// round 2
// speedup vs baseline: 1.2302x; 1.2302x over previous
#include <cuda_runtime.h>
#include <cuda_bf16.h>
#include <cstdint>

#define N_NODES 100000
#define N_EDGES 1600000
#define D 128
#define K2 256   // 2*D

// Scratch (no device mallocs allowed)
__device__ float g_sum[(size_t)N_NODES * D];   // 51.2 MB
__device__ int   g_deg[N_NODES];
__device__ float g_Wt[K2 * D];                 // W transposed: Wt[k][n] = W[n][k]

// ---------------------------------------------------------------------------
// Packed f32x2 helpers (sm_100+; bit-exact vs two fmaf)
// ---------------------------------------------------------------------------
__device__ __forceinline__ unsigned long long pack2(float lo, float hi) {
    unsigned long long r;
    asm("mov.b64 %0, {%1, %2};" : "=l"(r) : "f"(lo), "f"(hi));
    return r;
}
__device__ __forceinline__ void ffma2(unsigned long long& d,
                                      unsigned long long a,
                                      unsigned long long b) {
    asm("fma.rn.f32x2 %0, %1, %2, %0;" : "+l"(d) : "l"(a), "l"(b));
}
__device__ __forceinline__ float2 unpack2(unsigned long long v) {
    float2 r;
    asm("mov.b64 {%0, %1}, %2;" : "=f"(r.x), "=f"(r.y) : "l"(v));
    return r;
}

// ---------------------------------------------------------------------------
// Transpose W [128 out][256 in] -> Wt [256 k][128 n]
// ---------------------------------------------------------------------------
__global__ void transpose_W(const float* __restrict__ W) {
    int k = blockIdx.x;      // 0..255
    int n = threadIdx.x;     // 0..127
    g_Wt[k * D + n] = W[n * K2 + k];
}

// ---------------------------------------------------------------------------
// Scatter: one warp per edge, vector float4 atomics into g_sum, deg count.
// ---------------------------------------------------------------------------
__global__ void scatter_edges(const float* __restrict__ h,
                              const int* __restrict__ esrc,
                              const int* __restrict__ edst) {
    int gtid   = blockIdx.x * blockDim.x + threadIdx.x;
    int warp   = gtid >> 5;
    int lane   = threadIdx.x & 31;
    int nwarps = (gridDim.x * blockDim.x) >> 5;

    for (int e = warp; e < N_EDGES; e += nwarps) {
        int s = esrc[e];
        int d = edst[e];
        float4 v = *(const float4*)(h + (size_t)s * D + lane * 4);
        float* p = g_sum + (size_t)d * D + lane * 4;
        asm volatile("red.global.add.v4.f32 [%0], {%1,%2,%3,%4};"
                     :: "l"(p), "f"(v.x), "f"(v.y), "f"(v.z), "f"(v.w)
                     : "memory");
        if (lane == 0) atomicAdd(&g_deg[d], 1);
    }
}

// ---------------------------------------------------------------------------
// Fused GEMM (M=100000, N=128, K=256) + bias + L2 normalize + ReLU.
// Tile: 128 rows x 128 cols x 16 k. 256 threads, 8x8 micro-tile per thread.
// Inner product uses packed fma.rn.f32x2 (2 FMA lanes per fma-pipe slot).
// x[m][k] = h[m][k] for k<128, g_sum[m][k-128] * invdeg[m] for k>=128.
// ---------------------------------------------------------------------------
#define XS_LD 132   // padded row stride for xs[k][m]

__global__ void __launch_bounds__(256, 2)
fused_gemm_norm_relu(const float* __restrict__ h,
                     const float* __restrict__ bias,
                     float* __restrict__ out) {
    __shared__ float xs[16][XS_LD];        // [k][m] transposed x tile
    __shared__ float ws[16 * D];           // [k][n]
    __shared__ float invdeg[128];
    __shared__ float ssq[128][17];
    __shared__ float scale_s[128];

    const int tid = threadIdx.x;
    const int tx  = tid & 15;              // n group: cols tx*8 .. tx*8+7
    const int ty  = tid >> 4;              // m group: rows ty*8 .. ty*8+7
    const int m0  = blockIdx.x * 128;

    if (tid < 128) {
        int mg = m0 + tid;
        int dg = (mg < N_NODES) ? g_deg[mg] : 1;
        invdeg[tid] = 1.0f / (float)max(dg, 1);
    }
    __syncthreads();

    // acc2[mp][n]: rows (ty*8+2mp, ty*8+2mp+1), col tx*8+n
    unsigned long long acc2[4][8];
#pragma unroll
    for (int i = 0; i < 4; i++)
#pragma unroll
        for (int j = 0; j < 8; j++) acc2[i][j] = 0ull;

    // x loader: g = tid*2+i in [0,512): row ml=g>>2, kq=(g&3)*4 (gl-coalesced)
    int mls[2], kqs[2];
    float idgs[2];
#pragma unroll
    for (int i = 0; i < 2; i++) {
        int g = tid * 2 + i;
        mls[i] = g >> 2;
        kqs[i] = (g & 3) << 2;
        idgs[i] = invdeg[mls[i]];
    }
    int mg0 = m0 + mls[0]; if (mg0 >= N_NODES) mg0 = N_NODES - 1;
    int mg1 = m0 + mls[1]; if (mg1 >= N_NODES) mg1 = N_NODES - 1;
    const int mgs[2] = {mg0, mg1};

    for (int kk = 0; kk < K2; kk += 16) {
        // ---- load x tile (transposed into xs[k][m]) ----
#pragma unroll
        for (int i = 0; i < 2; i++) {
            float4 v;
            if (kk < D) {
                v = *(const float4*)(h + (size_t)mgs[i] * D + kk + kqs[i]);
            } else {
                float4 s = *(const float4*)(g_sum + (size_t)mgs[i] * D + (kk - D) + kqs[i]);
                float g = idgs[i];
                v = make_float4(s.x * g, s.y * g, s.z * g, s.w * g);
            }
            xs[kqs[i] + 0][mls[i]] = v.x;
            xs[kqs[i] + 1][mls[i]] = v.y;
            xs[kqs[i] + 2][mls[i]] = v.z;
            xs[kqs[i] + 3][mls[i]] = v.w;
        }

        // ---- load W tile from g_Wt (coalesced) ----
#pragma unroll
        for (int i = 0; i < 2; i++) {
            int f  = tid * 2 + i;            // 0..511 (float4 index)
            int kl = f >> 5;                 // 0..15
            int nn = (f & 31) << 2;          // 0..124
            *(float4*)&ws[kl * D + nn] =
                *(const float4*)(g_Wt + (size_t)(kk + kl) * D + nn);
        }
        __syncthreads();

        // ---- compute: 32 ffma2 per k per thread ----
#pragma unroll
        for (int k = 0; k < 16; k++) {
            float4 a0 = *(float4*)&xs[k][ty * 8];
            float4 a1 = *(float4*)&xs[k][ty * 8 + 4];
            unsigned long long a2[4];
            a2[0] = pack2(a0.x, a0.y);
            a2[1] = pack2(a0.z, a0.w);
            a2[2] = pack2(a1.x, a1.y);
            a2[3] = pack2(a1.z, a1.w);

            float4 b0 = *(float4*)&ws[k * D + tx * 8];
            float4 b1 = *(float4*)&ws[k * D + tx * 8 + 4];
            unsigned long long bb2[8];
            bb2[0] = pack2(b0.x, b0.x);
            bb2[1] = pack2(b0.y, b0.y);
            bb2[2] = pack2(b0.z, b0.z);
            bb2[3] = pack2(b0.w, b0.w);
            bb2[4] = pack2(b1.x, b1.x);
            bb2[5] = pack2(b1.y, b1.y);
            bb2[6] = pack2(b1.z, b1.z);
            bb2[7] = pack2(b1.w, b1.w);

#pragma unroll
            for (int mp = 0; mp < 4; mp++)
#pragma unroll
                for (int n = 0; n < 8; n++)
                    ffma2(acc2[mp][n], a2[mp], bb2[n]);
        }
        __syncthreads();
    }

    // ---- epilogue: bias, row sum-of-squares, normalize, relu, store ----
    float bb[8];
    *(float4*)&bb[0] = *(const float4*)(bias + tx * 8);
    *(float4*)&bb[4] = *(const float4*)(bias + tx * 8 + 4);

    float v[8][8];   // [row in micro-tile][col]
#pragma unroll
    for (int mp = 0; mp < 4; mp++) {
#pragma unroll
        for (int n = 0; n < 8; n++) {
            float2 p = unpack2(acc2[mp][n]);
            v[2 * mp + 0][n] = p.x + bb[n];
            v[2 * mp + 1][n] = p.y + bb[n];
        }
    }
#pragma unroll
    for (int i = 0; i < 8; i++) {
        float s = 0.0f;
#pragma unroll
        for (int n = 0; n < 8; n++) s += v[i][n] * v[i][n];
        ssq[ty * 8 + i][tx] = s;
    }
    __syncthreads();

    if (tid < 128) {
        float s = 0.0f;
#pragma unroll
        for (int j = 0; j < 16; j++) s += ssq[tid][j];
        float nrm = sqrtf(s);
        scale_s[tid] = 1.0f / fmaxf(nrm, 1e-12f);
    }
    __syncthreads();

#pragma unroll
    for (int i = 0; i < 8; i++) {
        int mgl = m0 + ty * 8 + i;
        if (mgl < N_NODES) {
            float sc = scale_s[ty * 8 + i];
            float4 o0, o1;
            o0.x = fmaxf(v[i][0] * sc, 0.0f);
            o0.y = fmaxf(v[i][1] * sc, 0.0f);
            o0.z = fmaxf(v[i][2] * sc, 0.0f);
            o0.w = fmaxf(v[i][3] * sc, 0.0f);
            o1.x = fmaxf(v[i][4] * sc, 0.0f);
            o1.y = fmaxf(v[i][5] * sc, 0.0f);
            o1.z = fmaxf(v[i][6] * sc, 0.0f);
            o1.w = fmaxf(v[i][7] * sc, 0.0f);
            *(float4*)(out + (size_t)mgl * D + tx * 8)     = o0;
            *(float4*)(out + (size_t)mgl * D + tx * 8 + 4) = o1;
        }
    }
}

// ---------------------------------------------------------------------------
extern "C" void kernel_launch(void* const* d_in, const int* in_sizes, int n_in,
                              void* d_out, int out_size) {
    const float* h    = (const float*)d_in[0];
    const float* W    = (const float*)d_in[1];
    const float* bias = (const float*)d_in[2];
    const int*   esrc = (const int*)d_in[3];
    const int*   edst = (const int*)d_in[4];
    float*       out  = (float*)d_out;

    void *p_sum = nullptr, *p_deg = nullptr;
    cudaGetSymbolAddress(&p_sum, g_sum);
    cudaGetSymbolAddress(&p_deg, g_deg);

    cudaMemsetAsync(p_sum, 0, sizeof(float) * (size_t)N_NODES * D, 0);
    cudaMemsetAsync(p_deg, 0, sizeof(int) * N_NODES, 0);

    transpose_W<<<K2, D>>>(W);
    scatter_edges<<<2368, 256>>>(h, esrc, edst);
    fused_gemm_norm_relu<<<(N_NODES + 127) / 128, 256>>>(h, bias, out);
}

// round 3
// speedup vs baseline: 1.4792x; 1.2024x over previous
#include <cuda_runtime.h>
#include <cuda_bf16.h>
#include <cstdint>

#define N_NODES 100000
#define N_EDGES 1600000
#define D 128
#define K2 256   // 2*D
#define NBLK 98  // ceil(N_NODES / 1024)

// Scratch (no device mallocs allowed)
__device__ float g_sum[(size_t)N_NODES * D];   // mean-aggregated c (51.2 MB)
__device__ int   g_deg[N_NODES];
__device__ int   g_cur[N_NODES];
__device__ int   g_rowstart[N_NODES + 1];
__device__ int   g_bsum[128];
__device__ int   g_csr[N_EDGES];
__device__ float g_Wt[K2 * D];                 // W transposed: Wt[k][n] = W[n][k]

// ---------------------------------------------------------------------------
// Packed f32x2 helpers (sm_100+; bit-exact vs two fmaf)
// ---------------------------------------------------------------------------
__device__ __forceinline__ unsigned long long pack2(float lo, float hi) {
    unsigned long long r;
    asm("mov.b64 %0, {%1, %2};" : "=l"(r) : "f"(lo), "f"(hi));
    return r;
}
__device__ __forceinline__ void ffma2(unsigned long long& d,
                                      unsigned long long a,
                                      unsigned long long b) {
    asm("fma.rn.f32x2 %0, %1, %2, %0;" : "+l"(d) : "l"(a), "l"(b));
}
__device__ __forceinline__ float2 unpack2(unsigned long long v) {
    float2 r;
    asm("mov.b64 {%0, %1}, %2;" : "=f"(r.x), "=f"(r.y) : "l"(v));
    return r;
}

// ---------------------------------------------------------------------------
// Transpose W [128 out][256 in] -> Wt [256 k][128 n]
// ---------------------------------------------------------------------------
__global__ void transpose_W(const float* __restrict__ W) {
    int k = blockIdx.x;
    int n = threadIdx.x;
    g_Wt[k * D + n] = W[n * K2 + k];
}

// ---------------------------------------------------------------------------
// CSR build: histogram -> block scans -> top scan -> offsets -> cursor fill
// ---------------------------------------------------------------------------
__global__ void hist_deg(const int* __restrict__ edst) {
    int i = blockIdx.x * blockDim.x + threadIdx.x;
    int stride = gridDim.x * blockDim.x;
    for (int e = i; e < N_EDGES; e += stride)
        atomicAdd(&g_deg[edst[e]], 1);
}

__global__ void scan_blocks() {
    __shared__ int wsum[32];
    int t = threadIdx.x, b = blockIdx.x;
    int i = b * 1024 + t;
    int v = (i < N_NODES) ? g_deg[i] : 0;
    int x = v;
#pragma unroll
    for (int o = 1; o < 32; o <<= 1) {
        int y = __shfl_up_sync(~0u, x, o);
        if ((t & 31) >= o) x += y;
    }
    if ((t & 31) == 31) wsum[t >> 5] = x;
    __syncthreads();
    if (t < 32) {
        int s = wsum[t];
#pragma unroll
        for (int o = 1; o < 32; o <<= 1) {
            int y = __shfl_up_sync(~0u, s, o);
            if (t >= o) s += y;
        }
        wsum[t] = s;
    }
    __syncthreads();
    int off = (t >= 32) ? wsum[(t >> 5) - 1] : 0;
    int incl = x + off;
    if (i < N_NODES) g_rowstart[i] = incl - v;   // exclusive
    if (t == 1023) g_bsum[b] = incl;             // block total
}

__global__ void scan_top() {
    __shared__ int s[128];
    int t = threadIdx.x;
    int mine = (t < NBLK) ? g_bsum[t] : 0;
    s[t] = mine;
    __syncthreads();
#pragma unroll
    for (int o = 1; o < 128; o <<= 1) {
        int v = (t >= o) ? s[t - o] : 0;
        __syncthreads();
        s[t] += v;
        __syncthreads();
    }
    g_bsum[t] = s[t] - mine;                     // exclusive block offset
}

__global__ void add_offsets() {
    int i = blockIdx.x * blockDim.x + threadIdx.x;
    if (i < N_NODES) g_rowstart[i] += g_bsum[i >> 10];
    if (i == 0) g_rowstart[N_NODES] = N_EDGES;
}

__global__ void fill_csr(const int* __restrict__ esrc,
                         const int* __restrict__ edst) {
    int i = blockIdx.x * blockDim.x + threadIdx.x;
    int stride = gridDim.x * blockDim.x;
    for (int e = i; e < N_EDGES; e += stride) {
        int d = edst[e];
        int p = atomicAdd(&g_cur[d], 1);
        g_csr[g_rowstart[d] + p] = esrc[e];
    }
}

// ---------------------------------------------------------------------------
// Segmented gather-mean: one warp per dst node, register accumulation,
// single 512B store (no atomics, no g_sum memset needed).
// ---------------------------------------------------------------------------
__global__ void __launch_bounds__(256)
gather_mean(const float* __restrict__ h) {
    int gtid = blockIdx.x * blockDim.x + threadIdx.x;
    int v    = gtid >> 5;
    int lane = threadIdx.x & 31;
    if (v >= N_NODES) return;

    int rs = g_rowstart[v];
    int re = g_rowstart[v + 1];

    float4 a0 = make_float4(0.f, 0.f, 0.f, 0.f);
    float4 a1 = make_float4(0.f, 0.f, 0.f, 0.f);

    int i = rs;
    for (; i + 1 < re; i += 2) {
        int s0 = g_csr[i];
        int s1 = g_csr[i + 1];
        float4 v0 = *(const float4*)(h + (size_t)s0 * D + lane * 4);
        float4 v1 = *(const float4*)(h + (size_t)s1 * D + lane * 4);
        a0.x += v0.x; a0.y += v0.y; a0.z += v0.z; a0.w += v0.w;
        a1.x += v1.x; a1.y += v1.y; a1.z += v1.z; a1.w += v1.w;
    }
    if (i < re) {
        int s0 = g_csr[i];
        float4 v0 = *(const float4*)(h + (size_t)s0 * D + lane * 4);
        a0.x += v0.x; a0.y += v0.y; a0.z += v0.z; a0.w += v0.w;
    }

    float inv = 1.0f / (float)max(re - rs, 1);
    float4 o;
    o.x = (a0.x + a1.x) * inv;
    o.y = (a0.y + a1.y) * inv;
    o.z = (a0.z + a1.z) * inv;
    o.w = (a0.w + a1.w) * inv;
    *(float4*)(g_sum + (size_t)v * D + lane * 4) = o;
}

// ---------------------------------------------------------------------------
// Fused GEMM (M=100000, N=128, K=256) + bias + L2 normalize + ReLU.
// 128x128x16 tile, 256 threads, 8x8 micro-tile, packed fma.rn.f32x2.
// x[m][k] = h[m][k] for k<128, g_sum[m][k-128] (already mean) for k>=128.
// ---------------------------------------------------------------------------
#define XS_LD 132

__global__ void __launch_bounds__(256, 2)
fused_gemm_norm_relu(const float* __restrict__ h,
                     const float* __restrict__ bias,
                     float* __restrict__ out) {
    __shared__ float xs[16][XS_LD];
    __shared__ float ws[16 * D];
    __shared__ float ssq[128][17];
    __shared__ float scale_s[128];

    const int tid = threadIdx.x;
    const int tx  = tid & 15;
    const int ty  = tid >> 4;
    const int m0  = blockIdx.x * 128;

    unsigned long long acc2[4][8];
#pragma unroll
    for (int i = 0; i < 4; i++)
#pragma unroll
        for (int j = 0; j < 8; j++) acc2[i][j] = 0ull;

    int mls[2], kqs[2];
#pragma unroll
    for (int i = 0; i < 2; i++) {
        int g = tid * 2 + i;
        mls[i] = g >> 2;
        kqs[i] = (g & 3) << 2;
    }
    int mg0 = m0 + mls[0]; if (mg0 >= N_NODES) mg0 = N_NODES - 1;
    int mg1 = m0 + mls[1]; if (mg1 >= N_NODES) mg1 = N_NODES - 1;
    const int mgs[2] = {mg0, mg1};

    for (int kk = 0; kk < K2; kk += 16) {
        const float* xsrc = (kk < D) ? h : g_sum;
        int kbase = (kk < D) ? kk : (kk - D);
#pragma unroll
        for (int i = 0; i < 2; i++) {
            float4 v = *(const float4*)(xsrc + (size_t)mgs[i] * D + kbase + kqs[i]);
            xs[kqs[i] + 0][mls[i]] = v.x;
            xs[kqs[i] + 1][mls[i]] = v.y;
            xs[kqs[i] + 2][mls[i]] = v.z;
            xs[kqs[i] + 3][mls[i]] = v.w;
        }
#pragma unroll
        for (int i = 0; i < 2; i++) {
            int f  = tid * 2 + i;
            int kl = f >> 5;
            int nn = (f & 31) << 2;
            *(float4*)&ws[kl * D + nn] =
                *(const float4*)(g_Wt + (size_t)(kk + kl) * D + nn);
        }
        __syncthreads();

#pragma unroll
        for (int k = 0; k < 16; k++) {
            float4 a0 = *(float4*)&xs[k][ty * 8];
            float4 a1 = *(float4*)&xs[k][ty * 8 + 4];
            unsigned long long a2[4];
            a2[0] = pack2(a0.x, a0.y);
            a2[1] = pack2(a0.z, a0.w);
            a2[2] = pack2(a1.x, a1.y);
            a2[3] = pack2(a1.z, a1.w);

            float4 b0 = *(float4*)&ws[k * D + tx * 8];
            float4 b1 = *(float4*)&ws[k * D + tx * 8 + 4];
            unsigned long long bb2[8];
            bb2[0] = pack2(b0.x, b0.x);
            bb2[1] = pack2(b0.y, b0.y);
            bb2[2] = pack2(b0.z, b0.z);
            bb2[3] = pack2(b0.w, b0.w);
            bb2[4] = pack2(b1.x, b1.x);
            bb2[5] = pack2(b1.y, b1.y);
            bb2[6] = pack2(b1.z, b1.z);
            bb2[7] = pack2(b1.w, b1.w);

#pragma unroll
            for (int mp = 0; mp < 4; mp++)
#pragma unroll
                for (int n = 0; n < 8; n++)
                    ffma2(acc2[mp][n], a2[mp], bb2[n]);
        }
        __syncthreads();
    }

    float bb[8];
    *(float4*)&bb[0] = *(const float4*)(bias + tx * 8);
    *(float4*)&bb[4] = *(const float4*)(bias + tx * 8 + 4);

    float v[8][8];
#pragma unroll
    for (int mp = 0; mp < 4; mp++) {
#pragma unroll
        for (int n = 0; n < 8; n++) {
            float2 p = unpack2(acc2[mp][n]);
            v[2 * mp + 0][n] = p.x + bb[n];
            v[2 * mp + 1][n] = p.y + bb[n];
        }
    }
#pragma unroll
    for (int i = 0; i < 8; i++) {
        float s = 0.0f;
#pragma unroll
        for (int n = 0; n < 8; n++) s += v[i][n] * v[i][n];
        ssq[ty * 8 + i][tx] = s;
    }
    __syncthreads();

    if (tid < 128) {
        float s = 0.0f;
#pragma unroll
        for (int j = 0; j < 16; j++) s += ssq[tid][j];
        float nrm = sqrtf(s);
        scale_s[tid] = 1.0f / fmaxf(nrm, 1e-12f);
    }
    __syncthreads();

#pragma unroll
    for (int i = 0; i < 8; i++) {
        int mgl = m0 + ty * 8 + i;
        if (mgl < N_NODES) {
            float sc = scale_s[ty * 8 + i];
            float4 o0, o1;
            o0.x = fmaxf(v[i][0] * sc, 0.0f);
            o0.y = fmaxf(v[i][1] * sc, 0.0f);
            o0.z = fmaxf(v[i][2] * sc, 0.0f);
            o0.w = fmaxf(v[i][3] * sc, 0.0f);
            o1.x = fmaxf(v[i][4] * sc, 0.0f);
            o1.y = fmaxf(v[i][5] * sc, 0.0f);
            o1.z = fmaxf(v[i][6] * sc, 0.0f);
            o1.w = fmaxf(v[i][7] * sc, 0.0f);
            *(float4*)(out + (size_t)mgl * D + tx * 8)     = o0;
            *(float4*)(out + (size_t)mgl * D + tx * 8 + 4) = o1;
        }
    }
}

// ---------------------------------------------------------------------------
extern "C" void kernel_launch(void* const* d_in, const int* in_sizes, int n_in,
                              void* d_out, int out_size) {
    const float* h    = (const float*)d_in[0];
    const float* W    = (const float*)d_in[1];
    const float* bias = (const float*)d_in[2];
    const int*   esrc = (const int*)d_in[3];
    const int*   edst = (const int*)d_in[4];
    float*       out  = (float*)d_out;

    void *p_deg = nullptr, *p_cur = nullptr;
    cudaGetSymbolAddress(&p_deg, g_deg);
    cudaGetSymbolAddress(&p_cur, g_cur);
    cudaMemsetAsync(p_deg, 0, sizeof(int) * N_NODES, 0);
    cudaMemsetAsync(p_cur, 0, sizeof(int) * N_NODES, 0);

    transpose_W<<<K2, D>>>(W);
    hist_deg<<<1184, 256>>>(edst);
    scan_blocks<<<NBLK, 1024>>>();
    scan_top<<<1, 128>>>();
    add_offsets<<<(N_NODES + 255) / 256, 256>>>();
    fill_csr<<<1184, 256>>>(esrc, edst);
    gather_mean<<<(N_NODES * 32 + 255) / 256, 256>>>(h);
    fused_gemm_norm_relu<<<(N_NODES + 127) / 128, 256>>>(h, bias, out);
}

// round 5
// speedup vs baseline: 1.8196x; 1.2301x over previous
#include <cuda_runtime.h>
#include <cuda_bf16.h>
#include <cstdint>

#define N_NODES 100000
#define N_EDGES 1600000
#define D 128
#define K2 256   // 2*D
#define NBLK 98  // ceil(N_NODES / 1024)

// Scratch (no device mallocs allowed)
__device__ float g_sum[(size_t)N_NODES * D];   // mean-aggregated c (51.2 MB)
__device__ int   g_deg[N_NODES];
__device__ int   g_cur[N_NODES];
__device__ int   g_rowstart[N_NODES + 1];
__device__ int   g_bsum[128];
__device__ int   g_csr[N_EDGES];
__device__ __nv_bfloat16 g_Bhi[D * K2];        // W split hi  [n][k] K-major
__device__ __nv_bfloat16 g_Blo[D * K2];        // W split lo

// ===========================================================================
// Helpers
// ===========================================================================
__device__ __forceinline__ uint32_t smem_u32(const void* p) {
    uint32_t a;
    asm("{ .reg .u64 t; cvta.to.shared.u64 t, %1; cvt.u32.u64 %0, t; }"
        : "=r"(a) : "l"(p));
    return a;
}
#define SW128(o) ((o) ^ (((o) >> 3) & 0x70))

__device__ __forceinline__ void ldsm_x4(uint32_t* r, uint32_t addr) {
    asm volatile("ldmatrix.sync.aligned.m8n8.x4.shared.b16 {%0,%1,%2,%3}, [%4];"
                 : "=r"(r[0]), "=r"(r[1]), "=r"(r[2]), "=r"(r[3]) : "r"(addr));
}
__device__ __forceinline__ void mma16816(float* c, const uint32_t* a,
                                         uint32_t b0, uint32_t b1) {
    asm volatile(
        "mma.sync.aligned.m16n8k16.row.col.f32.bf16.bf16.f32 "
        "{%0,%1,%2,%3}, {%4,%5,%6,%7}, {%8,%9}, {%0,%1,%2,%3};"
        : "+f"(c[0]), "+f"(c[1]), "+f"(c[2]), "+f"(c[3])
        : "r"(a[0]), "r"(a[1]), "r"(a[2]), "r"(a[3]), "r"(b0), "r"(b1));
}

// ---------------------------------------------------------------------------
// Split W into bf16 hi/lo. W is [128 out][256 in] row-major = [N][K] K-major.
// ---------------------------------------------------------------------------
__global__ void split_W(const float* __restrict__ W) {
    int i = blockIdx.x * blockDim.x + threadIdx.x;  // 0..32767
    float w = W[i];
    __nv_bfloat16 hi = __float2bfloat16(w);
    float lo = w - __bfloat162float(hi);
    g_Bhi[i] = hi;
    g_Blo[i] = __float2bfloat16(lo);
}

// ---------------------------------------------------------------------------
// CSR build: histogram -> block scans -> top scan -> offsets -> cursor fill
// ---------------------------------------------------------------------------
__global__ void hist_deg(const int* __restrict__ edst) {
    int i = blockIdx.x * blockDim.x + threadIdx.x;
    int stride = gridDim.x * blockDim.x;
    for (int e = i; e < N_EDGES; e += stride)
        atomicAdd(&g_deg[edst[e]], 1);
}

__global__ void scan_blocks() {
    __shared__ int wsum[32];
    int t = threadIdx.x, b = blockIdx.x;
    int i = b * 1024 + t;
    int v = (i < N_NODES) ? g_deg[i] : 0;
    int x = v;
#pragma unroll
    for (int o = 1; o < 32; o <<= 1) {
        int y = __shfl_up_sync(~0u, x, o);
        if ((t & 31) >= o) x += y;
    }
    if ((t & 31) == 31) wsum[t >> 5] = x;
    __syncthreads();
    if (t < 32) {
        int s = wsum[t];
#pragma unroll
        for (int o = 1; o < 32; o <<= 1) {
            int y = __shfl_up_sync(~0u, s, o);
            if (t >= o) s += y;
        }
        wsum[t] = s;
    }
    __syncthreads();
    int off = (t >= 32) ? wsum[(t >> 5) - 1] : 0;
    int incl = x + off;
    if (i < N_NODES) g_rowstart[i] = incl - v;
    if (t == 1023) g_bsum[b] = incl;
}

__global__ void scan_top() {
    __shared__ int s[128];
    int t = threadIdx.x;
    int mine = (t < NBLK) ? g_bsum[t] : 0;
    s[t] = mine;
    __syncthreads();
#pragma unroll
    for (int o = 1; o < 128; o <<= 1) {
        int v = (t >= o) ? s[t - o] : 0;
        __syncthreads();
        s[t] += v;
        __syncthreads();
    }
    g_bsum[t] = s[t] - mine;
}

__global__ void add_offsets() {
    int i = blockIdx.x * blockDim.x + threadIdx.x;
    if (i < N_NODES) g_rowstart[i] += g_bsum[i >> 10];
    if (i == 0) g_rowstart[N_NODES] = N_EDGES;
}

__global__ void fill_csr(const int* __restrict__ esrc,
                         const int* __restrict__ edst) {
    int i = blockIdx.x * blockDim.x + threadIdx.x;
    int stride = gridDim.x * blockDim.x;
    for (int e = i; e < N_EDGES; e += stride) {
        int d = edst[e];
        int p = atomicAdd(&g_cur[d], 1);
        g_csr[g_rowstart[d] + p] = esrc[e];
    }
}

// ---------------------------------------------------------------------------
// Segmented gather-mean: one warp per dst node, register accumulation.
// ---------------------------------------------------------------------------
__global__ void __launch_bounds__(256)
gather_mean(const float* __restrict__ h) {
    int gtid = blockIdx.x * blockDim.x + threadIdx.x;
    int v    = gtid >> 5;
    int lane = threadIdx.x & 31;
    if (v >= N_NODES) return;

    int rs = g_rowstart[v];
    int re = g_rowstart[v + 1];

    float4 a0 = make_float4(0.f, 0.f, 0.f, 0.f);
    float4 a1 = make_float4(0.f, 0.f, 0.f, 0.f);

    int i = rs;
    for (; i + 1 < re; i += 2) {
        int s0 = g_csr[i];
        int s1 = g_csr[i + 1];
        float4 v0 = *(const float4*)(h + (size_t)s0 * D + lane * 4);
        float4 v1 = *(const float4*)(h + (size_t)s1 * D + lane * 4);
        a0.x += v0.x; a0.y += v0.y; a0.z += v0.z; a0.w += v0.w;
        a1.x += v1.x; a1.y += v1.y; a1.z += v1.z; a1.w += v1.w;
    }
    if (i < re) {
        int s0 = g_csr[i];
        float4 v0 = *(const float4*)(h + (size_t)s0 * D + lane * 4);
        a0.x += v0.x; a0.y += v0.y; a0.z += v0.z; a0.w += v0.w;
    }

    float inv = 1.0f / (float)max(re - rs, 1);
    float4 o;
    o.x = (a0.x + a1.x) * inv;
    o.y = (a0.y + a1.y) * inv;
    o.z = (a0.z + a1.z) * inv;
    o.w = (a0.w + a1.w) * inv;
    *(float4*)(g_sum + (size_t)v * D + lane * 4) = o;
}

// ---------------------------------------------------------------------------
// mma.sync bf16 GEMM with 3-term split + fused bias/L2norm/relu epilogue.
// Block: 256 thr (8 warps), tile M=128 N=128 K=256 (4 chunks of 64).
// Warp tile 32m x 64n: warps laid out 4(m) x 2(n).
// SMEM: Whi/Wlo [4 chunks][128n][64k] bf16 SW128; A chunk hi/lo [128m][64k].
// ---------------------------------------------------------------------------
#define SMW_HI 0
#define SMW_LO 65536
#define SMA_HI 131072
#define SMA_LO (131072 + 16384)
#define SM_BIAS 163840
#define SM_SSQ 164352
#define SM_TOTAL 165376

__global__ void __launch_bounds__(256, 1)
gemm_mma(const float* __restrict__ h,
         const float* __restrict__ bias,
         float* __restrict__ out) {
    extern __shared__ char sm[];
    const uint32_t sb = smem_u32(sm);
    const int tid  = threadIdx.x;
    const int wid  = tid >> 5;
    const int lane = tid & 31;
    const int m0   = blockIdx.x * 128;
    const int mwarp = (wid >> 1) * 32;
    const int nwarp = (wid & 1) * 64;

    if (tid < 128) *(float*)(sm + SM_BIAS + tid * 4) = bias[tid];

    // ---- load whole W (hi/lo, 4 chunks) into SMEM, SW128 ----
    {
        int r = tid >> 1, half = tid & 1;
#pragma unroll
        for (int c = 0; c < 4; c++) {
#pragma unroll
            for (int j = 0; j < 4; j++) {
                uint4 vh = *(const uint4*)(g_Bhi + r * K2 + c * 64 + half * 32 + j * 8);
                uint4 vl = *(const uint4*)(g_Blo + r * K2 + c * 64 + half * 32 + j * 8);
                uint32_t sw = SW128((uint32_t)(r * 128 + half * 64 + j * 16));
                *(uint4*)(sm + SMW_HI + c * 16384 + sw) = vh;
                *(uint4*)(sm + SMW_LO + c * 16384 + sw) = vl;
            }
        }
    }

    const int r = tid >> 1, half = tid & 1;
    int mg = m0 + r;
    if (mg >= N_NODES) mg = N_NODES - 1;

    float acc[2][8][4];
#pragma unroll
    for (int mt = 0; mt < 2; mt++)
#pragma unroll
        for (int nt = 0; nt < 8; nt++)
#pragma unroll
            for (int q = 0; q < 4; q++) acc[mt][nt][q] = 0.0f;

    for (int ch = 0; ch < 4; ch++) {
        // ---- A chunk: fp32 -> bf16 hi/lo, SW128 ----
        const float* xsrc = (ch < 2) ? h : g_sum;
        const int kb = (ch & 1) * 64 + half * 32;
#pragma unroll
        for (int j = 0; j < 8; j++) {
            float4 v = *(const float4*)(xsrc + (size_t)mg * D + kb + j * 4);
            __nv_bfloat162 h0 = __float22bfloat162_rn(make_float2(v.x, v.y));
            __nv_bfloat162 h1 = __float22bfloat162_rn(make_float2(v.z, v.w));
            float2 hf0 = __bfloat1622float2(h0);
            float2 hf1 = __bfloat1622float2(h1);
            __nv_bfloat162 l0 = __float22bfloat162_rn(make_float2(v.x - hf0.x, v.y - hf0.y));
            __nv_bfloat162 l1 = __float22bfloat162_rn(make_float2(v.z - hf1.x, v.w - hf1.y));
            unsigned long long hu =
                (unsigned long long)*reinterpret_cast<uint32_t*>(&h0) |
                ((unsigned long long)*reinterpret_cast<uint32_t*>(&h1) << 32);
            unsigned long long lu =
                (unsigned long long)*reinterpret_cast<uint32_t*>(&l0) |
                ((unsigned long long)*reinterpret_cast<uint32_t*>(&l1) << 32);
            uint32_t sw = SW128((uint32_t)(r * 128 + half * 64 + j * 8));
            *(unsigned long long*)(sm + SMA_HI + sw) = hu;
            *(unsigned long long*)(sm + SMA_LO + sw) = lu;
        }
        __syncthreads();

#pragma unroll
        for (int ks = 0; ks < 4; ks++) {
            const uint32_t kc2 = ks * 32;   // byte col of k-step

            // A fragments (2 m-tiles, hi+lo)
            uint32_t ah[2][4], al[2][4];
#pragma unroll
            for (int mt = 0; mt < 2; mt++) {
                uint32_t rowoff = mwarp + mt * 16 + (lane & 7) + ((lane >> 3) & 1) * 8;
                uint32_t colb   = kc2 + ((lane >> 4) << 4);
                uint32_t sw = SW128(rowoff * 128 + colb);
                ldsm_x4(ah[mt], sb + SMA_HI + sw);
                ldsm_x4(al[mt], sb + SMA_LO + sw);
            }
            // B fragments (8 n8-tiles via 4 x4 loads, hi+lo)
            uint32_t bh[4][4], bl[4][4];
#pragma unroll
            for (int tp = 0; tp < 4; tp++) {
                uint32_t j = lane >> 3;
                uint32_t row = nwarp + tp * 16 + (lane & 7) + ((j >> 1) << 3);
                uint32_t colb = kc2 + ((j & 1) << 4);
                uint32_t sw = SW128(row * 128 + colb);
                ldsm_x4(bh[tp], sb + SMW_HI + ch * 16384 + sw);
                ldsm_x4(bl[tp], sb + SMW_LO + ch * 16384 + sw);
            }
            // MMAs: acc += Ahi*Bhi + Ahi*Blo + Alo*Bhi
#pragma unroll
            for (int mt = 0; mt < 2; mt++) {
#pragma unroll
                for (int nt = 0; nt < 8; nt++) {
                    uint32_t b0h = bh[nt >> 1][(nt & 1) * 2 + 0];
                    uint32_t b1h = bh[nt >> 1][(nt & 1) * 2 + 1];
                    uint32_t b0l = bl[nt >> 1][(nt & 1) * 2 + 0];
                    uint32_t b1l = bl[nt >> 1][(nt & 1) * 2 + 1];
                    mma16816(acc[mt][nt], ah[mt], b0h, b1h);
                    mma16816(acc[mt][nt], ah[mt], b0l, b1l);
                    mma16816(acc[mt][nt], al[mt], b0h, b1h);
                }
            }
        }
        __syncthreads();
    }

    // ---- epilogue: bias -> ssq -> normalize -> relu -> staged store ----
#pragma unroll
    for (int mt = 0; mt < 2; mt++)
#pragma unroll
        for (int nt = 0; nt < 8; nt++) {
            float2 bb = *(const float2*)(sm + SM_BIAS +
                                         (nwarp + nt * 8 + (lane & 3) * 2) * 4);
            acc[mt][nt][0] += bb.x;
            acc[mt][nt][1] += bb.y;
            acc[mt][nt][2] += bb.x;
            acc[mt][nt][3] += bb.y;
        }

    float pp[2][2] = {{0.f, 0.f}, {0.f, 0.f}};
#pragma unroll
    for (int mt = 0; mt < 2; mt++)
#pragma unroll
        for (int nt = 0; nt < 8; nt++) {
            pp[mt][0] += acc[mt][nt][0] * acc[mt][nt][0] +
                         acc[mt][nt][1] * acc[mt][nt][1];
            pp[mt][1] += acc[mt][nt][2] * acc[mt][nt][2] +
                         acc[mt][nt][3] * acc[mt][nt][3];
        }
#pragma unroll
    for (int off = 1; off <= 2; off <<= 1) {
#pragma unroll
        for (int mt = 0; mt < 2; mt++) {
            pp[mt][0] += __shfl_xor_sync(~0u, pp[mt][0], off);
            pp[mt][1] += __shfl_xor_sync(~0u, pp[mt][1], off);
        }
    }
    if ((lane & 3) == 0) {
#pragma unroll
        for (int mt = 0; mt < 2; mt++)
#pragma unroll
            for (int hh = 0; hh < 2; hh++) {
                int row = mwarp + mt * 16 + (lane >> 2) + hh * 8;
                *(float*)(sm + SM_SSQ + (wid & 1) * 512 + row * 4) = pp[mt][hh];
            }
    }
    __syncthreads();

    float sc[2][2];
#pragma unroll
    for (int mt = 0; mt < 2; mt++)
#pragma unroll
        for (int hh = 0; hh < 2; hh++) {
            int row = mwarp + mt * 16 + (lane >> 2) + hh * 8;
            float s = *(const float*)(sm + SM_SSQ + row * 4) +
                      *(const float*)(sm + SM_SSQ + 512 + row * 4);
            sc[mt][hh] = 1.0f / fmaxf(sqrtf(s), 1e-12f);
        }
    __syncthreads();   // ssq reads done before staging overwrites W region? (separate regions, but keep ordering cheap)

    // stage relu'd values into SMEM (reuse W region), 512B rows + XOR swizzle
#pragma unroll
    for (int mt = 0; mt < 2; mt++) {
#pragma unroll
        for (int nt = 0; nt < 8; nt++) {
            int coln = nwarp + nt * 8 + (lane & 3) * 2;
            int row0 = mwarp + mt * 16 + (lane >> 2);
            int row1 = row0 + 8;
            float2 v0, v1;
            v0.x = fmaxf(acc[mt][nt][0] * sc[mt][0], 0.0f);
            v0.y = fmaxf(acc[mt][nt][1] * sc[mt][0], 0.0f);
            v1.x = fmaxf(acc[mt][nt][2] * sc[mt][1], 0.0f);
            v1.y = fmaxf(acc[mt][nt][3] * sc[mt][1], 0.0f);
            *(float2*)(sm + row0 * 512 + ((coln * 4) ^ ((row0 & 7) << 4))) = v0;
            *(float2*)(sm + row1 * 512 + ((coln * 4) ^ ((row1 & 7) << 4))) = v1;
        }
    }
    __syncthreads();

    // coalesced copy out
#pragma unroll
    for (int i = 0; i < 16; i++) {
        int idx = tid + i * 256;
        int rr = idx >> 5;
        int p  = idx & 31;
        int mgl = m0 + rr;
        if (mgl < N_NODES) {
            float4 o = *(const float4*)(sm + rr * 512 + ((p * 16) ^ ((rr & 7) << 4)));
            *(float4*)(out + (size_t)mgl * D + p * 4) = o;
        }
    }
}

// ---------------------------------------------------------------------------
extern "C" void kernel_launch(void* const* d_in, const int* in_sizes, int n_in,
                              void* d_out, int out_size) {
    const float* h    = (const float*)d_in[0];
    const float* W    = (const float*)d_in[1];
    const float* bias = (const float*)d_in[2];
    const int*   esrc = (const int*)d_in[3];
    const int*   edst = (const int*)d_in[4];
    float*       out  = (float*)d_out;

    void *p_deg = nullptr, *p_cur = nullptr;
    cudaGetSymbolAddress(&p_deg, g_deg);
    cudaGetSymbolAddress(&p_cur, g_cur);
    cudaMemsetAsync(p_deg, 0, sizeof(int) * N_NODES, 0);
    cudaMemsetAsync(p_cur, 0, sizeof(int) * N_NODES, 0);

    cudaFuncSetAttribute(gemm_mma, cudaFuncAttributeMaxDynamicSharedMemorySize,
                         SM_TOTAL);

    split_W<<<128, 256>>>(W);
    hist_deg<<<1184, 256>>>(edst);
    scan_blocks<<<NBLK, 1024>>>();
    scan_top<<<1, 128>>>();
    add_offsets<<<(N_NODES + 255) / 256, 256>>>();
    fill_csr<<<1184, 256>>>(esrc, edst);
    gather_mean<<<(N_NODES * 32 + 255) / 256, 256>>>(h);
    gemm_mma<<<(N_NODES + 127) / 128, 256, SM_TOTAL>>>(h, bias, out);
}

// round 6
// speedup vs baseline: 1.8907x; 1.0391x over previous
#include <cuda_runtime.h>
#include <cuda_bf16.h>
#include <cuda_fp16.h>
#include <cstdint>

#define N_NODES 100000
#define N_EDGES 1600000
#define D 128
#define K2 256   // 2*D
#define NBLK 98  // ceil(N_NODES / 1024)

// Scratch (no device mallocs allowed)
__device__ float   g_sum[(size_t)N_NODES * D];   // mean-aggregated c (51.2 MB)
__device__ __half2 g_h16[(size_t)N_NODES * (D / 2)];  // fp16 h (25.6 MB)
__device__ int   g_deg[N_NODES];
__device__ int   g_cur[N_NODES];
__device__ int   g_rowstart[N_NODES];
__device__ int   g_bsum[128];
__device__ int   g_csr[N_EDGES];
__device__ __nv_bfloat16 g_Bhi[D * K2];        // W split hi  [n][k] K-major
__device__ __nv_bfloat16 g_Blo[D * K2];        // W split lo

// ===========================================================================
// Helpers
// ===========================================================================
__device__ __forceinline__ uint32_t smem_u32(const void* p) {
    uint32_t a;
    asm("{ .reg .u64 t; cvta.to.shared.u64 t, %1; cvt.u32.u64 %0, t; }"
        : "=r"(a) : "l"(p));
    return a;
}
#define SW128(o) ((o) ^ (((o) >> 3) & 0x70))

__device__ __forceinline__ void ldsm_x4(uint32_t* r, uint32_t addr) {
    asm volatile("ldmatrix.sync.aligned.m8n8.x4.shared.b16 {%0,%1,%2,%3}, [%4];"
                 : "=r"(r[0]), "=r"(r[1]), "=r"(r[2]), "=r"(r[3]) : "r"(addr));
}
__device__ __forceinline__ void mma16816(float* c, const uint32_t* a,
                                         uint32_t b0, uint32_t b1) {
    asm volatile(
        "mma.sync.aligned.m16n8k16.row.col.f32.bf16.bf16.f32 "
        "{%0,%1,%2,%3}, {%4,%5,%6,%7}, {%8,%9}, {%0,%1,%2,%3};"
        : "+f"(c[0]), "+f"(c[1]), "+f"(c[2]), "+f"(c[3])
        : "r"(a[0]), "r"(a[1]), "r"(a[2]), "r"(a[3]), "r"(b0), "r"(b1));
}

// ---------------------------------------------------------------------------
// Split W into bf16 hi/lo. W is [128 out][256 in] row-major = [N][K] K-major.
// ---------------------------------------------------------------------------
__global__ void split_W(const float* __restrict__ W) {
    int i = blockIdx.x * blockDim.x + threadIdx.x;  // 0..32767
    float w = W[i];
    __nv_bfloat16 hi = __float2bfloat16(w);
    float lo = w - __bfloat162float(hi);
    g_Bhi[i] = hi;
    g_Blo[i] = __float2bfloat16(lo);
}

// ---------------------------------------------------------------------------
// Convert h (fp32) -> g_h16 (fp16), vectorized.
// ---------------------------------------------------------------------------
__global__ void h_to_fp16(const float* __restrict__ h) {
    int i = blockIdx.x * blockDim.x + threadIdx.x;   // float4 index
    int stride = gridDim.x * blockDim.x;
    const int total = N_NODES * (D / 4);             // 3.2M
    for (; i < total; i += stride) {
        float4 v = *(const float4*)(h + (size_t)i * 4);
        __half2 a = __floats2half2_rn(v.x, v.y);
        __half2 b = __floats2half2_rn(v.z, v.w);
        uint2 u;
        u.x = *reinterpret_cast<uint32_t*>(&a);
        u.y = *reinterpret_cast<uint32_t*>(&b);
        *(uint2*)(g_h16 + (size_t)i * 2) = u;
    }
}

// ---------------------------------------------------------------------------
// CSR build: histogram -> block scans -> top scan -> cursor fill
// (top-level block offsets folded into consumers via g_bsum)
// ---------------------------------------------------------------------------
__global__ void hist_deg(const int* __restrict__ edst) {
    int i = blockIdx.x * blockDim.x + threadIdx.x;
    int stride = gridDim.x * blockDim.x;
    for (int e = i; e < N_EDGES; e += stride)
        atomicAdd(&g_deg[edst[e]], 1);
}

__global__ void scan_blocks() {
    __shared__ int wsum[32];
    int t = threadIdx.x, b = blockIdx.x;
    int i = b * 1024 + t;
    int v = (i < N_NODES) ? g_deg[i] : 0;
    int x = v;
#pragma unroll
    for (int o = 1; o < 32; o <<= 1) {
        int y = __shfl_up_sync(~0u, x, o);
        if ((t & 31) >= o) x += y;
    }
    if ((t & 31) == 31) wsum[t >> 5] = x;
    __syncthreads();
    if (t < 32) {
        int s = wsum[t];
#pragma unroll
        for (int o = 1; o < 32; o <<= 1) {
            int y = __shfl_up_sync(~0u, s, o);
            if (t >= o) s += y;
        }
        wsum[t] = s;
    }
    __syncthreads();
    int off = (t >= 32) ? wsum[(t >> 5) - 1] : 0;
    int incl = x + off;
    if (i < N_NODES) g_rowstart[i] = incl - v;   // exclusive within block
    if (t == 1023) g_bsum[b] = incl;
}

__global__ void scan_top() {
    __shared__ int s[128];
    int t = threadIdx.x;
    int mine = (t < NBLK) ? g_bsum[t] : 0;
    s[t] = mine;
    __syncthreads();
#pragma unroll
    for (int o = 1; o < 128; o <<= 1) {
        int v = (t >= o) ? s[t - o] : 0;
        __syncthreads();
        s[t] += v;
        __syncthreads();
    }
    g_bsum[t] = s[t] - mine;                     // exclusive block offset
}

__global__ void fill_csr(const int* __restrict__ esrc,
                         const int* __restrict__ edst) {
    int i = blockIdx.x * blockDim.x + threadIdx.x;
    int stride = gridDim.x * blockDim.x;
    for (int e = i; e < N_EDGES; e += stride) {
        int d = edst[e];
        int p = atomicAdd(&g_cur[d], 1);
        g_csr[g_rowstart[d] + g_bsum[d >> 10] + p] = esrc[e];
    }
}

// ---------------------------------------------------------------------------
// Segmented gather-mean over fp16 h: one warp per dst node, fp32 register
// accumulation, single 512B fp32 store.
// ---------------------------------------------------------------------------
__global__ void __launch_bounds__(256)
gather_mean16() {
    int gtid = blockIdx.x * blockDim.x + threadIdx.x;
    int v    = gtid >> 5;
    int lane = threadIdx.x & 31;
    if (v >= N_NODES) return;

    int deg = g_deg[v];
    int rs  = g_rowstart[v] + g_bsum[v >> 10];
    int re  = rs + deg;

    // each lane owns 4 floats: half2 pair at column lane*2, lane*2+1
    float4 a0 = make_float4(0.f, 0.f, 0.f, 0.f);
    float4 a1 = make_float4(0.f, 0.f, 0.f, 0.f);

    int i = rs;
    for (; i + 1 < re; i += 2) {
        int s0 = g_csr[i];
        int s1 = g_csr[i + 1];
        uint2 u0 = *(const uint2*)(g_h16 + (size_t)s0 * 64 + lane * 2);
        uint2 u1 = *(const uint2*)(g_h16 + (size_t)s1 * 64 + lane * 2);
        float2 f0 = __half22float2(*reinterpret_cast<__half2*>(&u0.x));
        float2 f1 = __half22float2(*reinterpret_cast<__half2*>(&u0.y));
        float2 f2 = __half22float2(*reinterpret_cast<__half2*>(&u1.x));
        float2 f3 = __half22float2(*reinterpret_cast<__half2*>(&u1.y));
        a0.x += f0.x; a0.y += f0.y; a0.z += f1.x; a0.w += f1.y;
        a1.x += f2.x; a1.y += f2.y; a1.z += f3.x; a1.w += f3.y;
    }
    if (i < re) {
        int s0 = g_csr[i];
        uint2 u0 = *(const uint2*)(g_h16 + (size_t)s0 * 64 + lane * 2);
        float2 f0 = __half22float2(*reinterpret_cast<__half2*>(&u0.x));
        float2 f1 = __half22float2(*reinterpret_cast<__half2*>(&u0.y));
        a0.x += f0.x; a0.y += f0.y; a0.z += f1.x; a0.w += f1.y;
    }

    float inv = 1.0f / (float)max(deg, 1);
    float4 o;
    o.x = (a0.x + a1.x) * inv;
    o.y = (a0.y + a1.y) * inv;
    o.z = (a0.z + a1.z) * inv;
    o.w = (a0.w + a1.w) * inv;
    *(float4*)(g_sum + (size_t)v * D + lane * 4) = o;
}

// ---------------------------------------------------------------------------
// mma.sync bf16 GEMM with 3-term split + fused bias/L2norm/relu epilogue.
// (unchanged from R5)
// ---------------------------------------------------------------------------
#define SMW_HI 0
#define SMW_LO 65536
#define SMA_HI 131072
#define SMA_LO (131072 + 16384)
#define SM_BIAS 163840
#define SM_SSQ 164352
#define SM_TOTAL 165376

__global__ void __launch_bounds__(256, 1)
gemm_mma(const float* __restrict__ h,
         const float* __restrict__ bias,
         float* __restrict__ out) {
    extern __shared__ char sm[];
    const uint32_t sb = smem_u32(sm);
    const int tid  = threadIdx.x;
    const int wid  = tid >> 5;
    const int lane = tid & 31;
    const int m0   = blockIdx.x * 128;
    const int mwarp = (wid >> 1) * 32;
    const int nwarp = (wid & 1) * 64;

    if (tid < 128) *(float*)(sm + SM_BIAS + tid * 4) = bias[tid];

    {
        int r = tid >> 1, half = tid & 1;
#pragma unroll
        for (int c = 0; c < 4; c++) {
#pragma unroll
            for (int j = 0; j < 4; j++) {
                uint4 vh = *(const uint4*)(g_Bhi + r * K2 + c * 64 + half * 32 + j * 8);
                uint4 vl = *(const uint4*)(g_Blo + r * K2 + c * 64 + half * 32 + j * 8);
                uint32_t sw = SW128((uint32_t)(r * 128 + half * 64 + j * 16));
                *(uint4*)(sm + SMW_HI + c * 16384 + sw) = vh;
                *(uint4*)(sm + SMW_LO + c * 16384 + sw) = vl;
            }
        }
    }

    const int r = tid >> 1, half = tid & 1;
    int mg = m0 + r;
    if (mg >= N_NODES) mg = N_NODES - 1;

    float acc[2][8][4];
#pragma unroll
    for (int mt = 0; mt < 2; mt++)
#pragma unroll
        for (int nt = 0; nt < 8; nt++)
#pragma unroll
            for (int q = 0; q < 4; q++) acc[mt][nt][q] = 0.0f;

    for (int ch = 0; ch < 4; ch++) {
        const float* xsrc = (ch < 2) ? h : g_sum;
        const int kb = (ch & 1) * 64 + half * 32;
#pragma unroll
        for (int j = 0; j < 8; j++) {
            float4 v = *(const float4*)(xsrc + (size_t)mg * D + kb + j * 4);
            __nv_bfloat162 h0 = __float22bfloat162_rn(make_float2(v.x, v.y));
            __nv_bfloat162 h1 = __float22bfloat162_rn(make_float2(v.z, v.w));
            float2 hf0 = __bfloat1622float2(h0);
            float2 hf1 = __bfloat1622float2(h1);
            __nv_bfloat162 l0 = __float22bfloat162_rn(make_float2(v.x - hf0.x, v.y - hf0.y));
            __nv_bfloat162 l1 = __float22bfloat162_rn(make_float2(v.z - hf1.x, v.w - hf1.y));
            unsigned long long hu =
                (unsigned long long)*reinterpret_cast<uint32_t*>(&h0) |
                ((unsigned long long)*reinterpret_cast<uint32_t*>(&h1) << 32);
            unsigned long long lu =
                (unsigned long long)*reinterpret_cast<uint32_t*>(&l0) |
                ((unsigned long long)*reinterpret_cast<uint32_t*>(&l1) << 32);
            uint32_t sw = SW128((uint32_t)(r * 128 + half * 64 + j * 8));
            *(unsigned long long*)(sm + SMA_HI + sw) = hu;
            *(unsigned long long*)(sm + SMA_LO + sw) = lu;
        }
        __syncthreads();

#pragma unroll
        for (int ks = 0; ks < 4; ks++) {
            const uint32_t kc2 = ks * 32;

            uint32_t ah[2][4], al[2][4];
#pragma unroll
            for (int mt = 0; mt < 2; mt++) {
                uint32_t rowoff = mwarp + mt * 16 + (lane & 7) + ((lane >> 3) & 1) * 8;
                uint32_t colb   = kc2 + ((lane >> 4) << 4);
                uint32_t sw = SW128(rowoff * 128 + colb);
                ldsm_x4(ah[mt], sb + SMA_HI + sw);
                ldsm_x4(al[mt], sb + SMA_LO + sw);
            }
            uint32_t bh[4][4], bl[4][4];
#pragma unroll
            for (int tp = 0; tp < 4; tp++) {
                uint32_t j = lane >> 3;
                uint32_t row = nwarp + tp * 16 + (lane & 7) + ((j >> 1) << 3);
                uint32_t colb = kc2 + ((j & 1) << 4);
                uint32_t sw = SW128(row * 128 + colb);
                ldsm_x4(bh[tp], sb + SMW_HI + ch * 16384 + sw);
                ldsm_x4(bl[tp], sb + SMW_LO + ch * 16384 + sw);
            }
#pragma unroll
            for (int mt = 0; mt < 2; mt++) {
#pragma unroll
                for (int nt = 0; nt < 8; nt++) {
                    uint32_t b0h = bh[nt >> 1][(nt & 1) * 2 + 0];
                    uint32_t b1h = bh[nt >> 1][(nt & 1) * 2 + 1];
                    uint32_t b0l = bl[nt >> 1][(nt & 1) * 2 + 0];
                    uint32_t b1l = bl[nt >> 1][(nt & 1) * 2 + 1];
                    mma16816(acc[mt][nt], ah[mt], b0h, b1h);
                    mma16816(acc[mt][nt], ah[mt], b0l, b1l);
                    mma16816(acc[mt][nt], al[mt], b0h, b1h);
                }
            }
        }
        __syncthreads();
    }

#pragma unroll
    for (int mt = 0; mt < 2; mt++)
#pragma unroll
        for (int nt = 0; nt < 8; nt++) {
            float2 bb = *(const float2*)(sm + SM_BIAS +
                                         (nwarp + nt * 8 + (lane & 3) * 2) * 4);
            acc[mt][nt][0] += bb.x;
            acc[mt][nt][1] += bb.y;
            acc[mt][nt][2] += bb.x;
            acc[mt][nt][3] += bb.y;
        }

    float pp[2][2] = {{0.f, 0.f}, {0.f, 0.f}};
#pragma unroll
    for (int mt = 0; mt < 2; mt++)
#pragma unroll
        for (int nt = 0; nt < 8; nt++) {
            pp[mt][0] += acc[mt][nt][0] * acc[mt][nt][0] +
                         acc[mt][nt][1] * acc[mt][nt][1];
            pp[mt][1] += acc[mt][nt][2] * acc[mt][nt][2] +
                         acc[mt][nt][3] * acc[mt][nt][3];
        }
#pragma unroll
    for (int off = 1; off <= 2; off <<= 1) {
#pragma unroll
        for (int mt = 0; mt < 2; mt++) {
            pp[mt][0] += __shfl_xor_sync(~0u, pp[mt][0], off);
            pp[mt][1] += __shfl_xor_sync(~0u, pp[mt][1], off);
        }
    }
    if ((lane & 3) == 0) {
#pragma unroll
        for (int mt = 0; mt < 2; mt++)
#pragma unroll
            for (int hh = 0; hh < 2; hh++) {
                int row = mwarp + mt * 16 + (lane >> 2) + hh * 8;
                *(float*)(sm + SM_SSQ + (wid & 1) * 512 + row * 4) = pp[mt][hh];
            }
    }
    __syncthreads();

    float sc[2][2];
#pragma unroll
    for (int mt = 0; mt < 2; mt++)
#pragma unroll
        for (int hh = 0; hh < 2; hh++) {
            int row = mwarp + mt * 16 + (lane >> 2) + hh * 8;
            float s = *(const float*)(sm + SM_SSQ + row * 4) +
                      *(const float*)(sm + SM_SSQ + 512 + row * 4);
            sc[mt][hh] = 1.0f / fmaxf(sqrtf(s), 1e-12f);
        }
    __syncthreads();

#pragma unroll
    for (int mt = 0; mt < 2; mt++) {
#pragma unroll
        for (int nt = 0; nt < 8; nt++) {
            int coln = nwarp + nt * 8 + (lane & 3) * 2;
            int row0 = mwarp + mt * 16 + (lane >> 2);
            int row1 = row0 + 8;
            float2 v0, v1;
            v0.x = fmaxf(acc[mt][nt][0] * sc[mt][0], 0.0f);
            v0.y = fmaxf(acc[mt][nt][1] * sc[mt][0], 0.0f);
            v1.x = fmaxf(acc[mt][nt][2] * sc[mt][1], 0.0f);
            v1.y = fmaxf(acc[mt][nt][3] * sc[mt][1], 0.0f);
            *(float2*)(sm + row0 * 512 + ((coln * 4) ^ ((row0 & 7) << 4))) = v0;
            *(float2*)(sm + row1 * 512 + ((coln * 4) ^ ((row1 & 7) << 4))) = v1;
        }
    }
    __syncthreads();

#pragma unroll
    for (int i = 0; i < 16; i++) {
        int idx = tid + i * 256;
        int rr = idx >> 5;
        int p  = idx & 31;
        int mgl = m0 + rr;
        if (mgl < N_NODES) {
            float4 o = *(const float4*)(sm + rr * 512 + ((p * 16) ^ ((rr & 7) << 4)));
            *(float4*)(out + (size_t)mgl * D + p * 4) = o;
        }
    }
}

// ---------------------------------------------------------------------------
extern "C" void kernel_launch(void* const* d_in, const int* in_sizes, int n_in,
                              void* d_out, int out_size) {
    const float* h    = (const float*)d_in[0];
    const float* W    = (const float*)d_in[1];
    const float* bias = (const float*)d_in[2];
    const int*   esrc = (const int*)d_in[3];
    const int*   edst = (const int*)d_in[4];
    float*       out  = (float*)d_out;

    void *p_deg = nullptr, *p_cur = nullptr;
    cudaGetSymbolAddress(&p_deg, g_deg);
    cudaGetSymbolAddress(&p_cur, g_cur);
    cudaMemsetAsync(p_deg, 0, sizeof(int) * N_NODES, 0);
    cudaMemsetAsync(p_cur, 0, sizeof(int) * N_NODES, 0);

    cudaFuncSetAttribute(gemm_mma, cudaFuncAttributeMaxDynamicSharedMemorySize,
                         SM_TOTAL);

    split_W<<<128, 256>>>(W);
    h_to_fp16<<<1600, 256>>>(h);
    hist_deg<<<1184, 256>>>(edst);
    scan_blocks<<<NBLK, 1024>>>();
    scan_top<<<1, 128>>>();
    fill_csr<<<1184, 256>>>(esrc, edst);
    gather_mean16<<<(N_NODES * 32 + 255) / 256, 256>>>();
    gemm_mma<<<(N_NODES + 127) / 128, 256, SM_TOTAL>>>(h, bias, out);
}

// round 7
// speedup vs baseline: 2.0422x; 1.0801x over previous
#include <cuda_runtime.h>
#include <cuda_bf16.h>
#include <cuda_fp16.h>
#include <cstdint>

#define N_NODES 100000
#define N_EDGES 1600000
#define D 128
#define K2 256   // 2*D
#define NBLK 98  // ceil(N_NODES / 1024)

// Scratch (no device mallocs allowed)
__device__ __half2 g_h16[(size_t)N_NODES * (D / 2)];  // fp16 h (25.6 MB)
__device__ __half2 g_c16[(size_t)N_NODES * (D / 2)];  // fp16 c (25.6 MB)
__device__ int   g_deg[N_NODES];
__device__ int   g_cur[N_NODES];
__device__ int   g_rowstart[N_NODES];
__device__ int   g_bsum[128];
__device__ int   g_csr[N_EDGES];
__device__ __nv_bfloat16 g_Bhi[D * K2];        // W split hi  [n][k] K-major (full K)
__device__ __nv_bfloat16 g_Blo[D * K2];        // W split lo
__device__ __half g_Bfh[D * D];                // W fp16 hi, k in [128,256)
__device__ __half g_Bfl[D * D];                // W fp16 lo

// ===========================================================================
// Helpers
// ===========================================================================
__device__ __forceinline__ uint32_t smem_u32(const void* p) {
    uint32_t a;
    asm("{ .reg .u64 t; cvta.to.shared.u64 t, %1; cvt.u32.u64 %0, t; }"
        : "=r"(a) : "l"(p));
    return a;
}
#define SW128(o) ((o) ^ (((o) >> 3) & 0x70))

__device__ __forceinline__ void ldsm_x4(uint32_t* r, uint32_t addr) {
    asm volatile("ldmatrix.sync.aligned.m8n8.x4.shared.b16 {%0,%1,%2,%3}, [%4];"
                 : "=r"(r[0]), "=r"(r[1]), "=r"(r[2]), "=r"(r[3]) : "r"(addr));
}
__device__ __forceinline__ void mma_bf16(float* c, const uint32_t* a,
                                         uint32_t b0, uint32_t b1) {
    asm volatile(
        "mma.sync.aligned.m16n8k16.row.col.f32.bf16.bf16.f32 "
        "{%0,%1,%2,%3}, {%4,%5,%6,%7}, {%8,%9}, {%0,%1,%2,%3};"
        : "+f"(c[0]), "+f"(c[1]), "+f"(c[2]), "+f"(c[3])
        : "r"(a[0]), "r"(a[1]), "r"(a[2]), "r"(a[3]), "r"(b0), "r"(b1));
}
__device__ __forceinline__ void mma_f16(float* c, const uint32_t* a,
                                        uint32_t b0, uint32_t b1) {
    asm volatile(
        "mma.sync.aligned.m16n8k16.row.col.f32.f16.f16.f32 "
        "{%0,%1,%2,%3}, {%4,%5,%6,%7}, {%8,%9}, {%0,%1,%2,%3};"
        : "+f"(c[0]), "+f"(c[1]), "+f"(c[2]), "+f"(c[3])
        : "r"(a[0]), "r"(a[1]), "r"(a[2]), "r"(a[3]), "r"(b0), "r"(b1));
}

// ---------------------------------------------------------------------------
// Split W: bf16 hi/lo (all K) + fp16 hi/lo (K in [128,256) for the c-half).
// ---------------------------------------------------------------------------
__global__ void split_W(const float* __restrict__ W) {
    int i = blockIdx.x * blockDim.x + threadIdx.x;  // 0..32767
    float w = W[i];
    __nv_bfloat16 hi = __float2bfloat16(w);
    g_Bhi[i] = hi;
    g_Blo[i] = __float2bfloat16(w - __bfloat162float(hi));
    int k = i & 255;
    if (k >= 128) {
        int n = i >> 8;
        __half fh = __float2half(w);
        g_Bfh[n * 128 + (k - 128)] = fh;
        g_Bfl[n * 128 + (k - 128)] = __float2half(w - __half2float(fh));
    }
}

// ---------------------------------------------------------------------------
// Convert h (fp32) -> g_h16 (fp16), vectorized.
// ---------------------------------------------------------------------------
__global__ void h_to_fp16(const float* __restrict__ h) {
    int i = blockIdx.x * blockDim.x + threadIdx.x;   // float4 index
    int stride = gridDim.x * blockDim.x;
    const int total = N_NODES * (D / 4);             // 3.2M
    for (; i < total; i += stride) {
        float4 v = *(const float4*)(h + (size_t)i * 4);
        __half2 a = __floats2half2_rn(v.x, v.y);
        __half2 b = __floats2half2_rn(v.z, v.w);
        uint2 u;
        u.x = *reinterpret_cast<uint32_t*>(&a);
        u.y = *reinterpret_cast<uint32_t*>(&b);
        *(uint2*)(g_h16 + (size_t)i * 2) = u;
    }
}

// ---------------------------------------------------------------------------
// CSR build: histogram -> block scans -> top scan -> cursor fill
// ---------------------------------------------------------------------------
__global__ void hist_deg(const int* __restrict__ edst) {
    int i = blockIdx.x * blockDim.x + threadIdx.x;
    int stride = gridDim.x * blockDim.x;
    for (int e = i; e < N_EDGES; e += stride)
        atomicAdd(&g_deg[edst[e]], 1);
}

__global__ void scan_blocks() {
    __shared__ int wsum[32];
    int t = threadIdx.x, b = blockIdx.x;
    int i = b * 1024 + t;
    int v = (i < N_NODES) ? g_deg[i] : 0;
    int x = v;
#pragma unroll
    for (int o = 1; o < 32; o <<= 1) {
        int y = __shfl_up_sync(~0u, x, o);
        if ((t & 31) >= o) x += y;
    }
    if ((t & 31) == 31) wsum[t >> 5] = x;
    __syncthreads();
    if (t < 32) {
        int s = wsum[t];
#pragma unroll
        for (int o = 1; o < 32; o <<= 1) {
            int y = __shfl_up_sync(~0u, s, o);
            if (t >= o) s += y;
        }
        wsum[t] = s;
    }
    __syncthreads();
    int off = (t >= 32) ? wsum[(t >> 5) - 1] : 0;
    int incl = x + off;
    if (i < N_NODES) g_rowstart[i] = incl - v;
    if (t == 1023) g_bsum[b] = incl;
}

__global__ void scan_top() {
    __shared__ int s[128];
    int t = threadIdx.x;
    int mine = (t < NBLK) ? g_bsum[t] : 0;
    s[t] = mine;
    __syncthreads();
#pragma unroll
    for (int o = 1; o < 128; o <<= 1) {
        int v = (t >= o) ? s[t - o] : 0;
        __syncthreads();
        s[t] += v;
        __syncthreads();
    }
    g_bsum[t] = s[t] - mine;
}

__global__ void fill_csr(const int* __restrict__ esrc,
                         const int* __restrict__ edst) {
    int i = blockIdx.x * blockDim.x + threadIdx.x;
    int stride = gridDim.x * blockDim.x;
    for (int e = i; e < N_EDGES; e += stride) {
        int d = edst[e];
        int p = atomicAdd(&g_cur[d], 1);
        g_csr[g_rowstart[d] + g_bsum[d >> 10] + p] = esrc[e];
    }
}

// ---------------------------------------------------------------------------
// Segmented gather-mean over fp16 h: one warp per dst node, 4 edges in
// flight, fp32 accumulation, fp16 output row (256B).
// ---------------------------------------------------------------------------
__global__ void __launch_bounds__(256)
gather_mean16() {
    int gtid = blockIdx.x * blockDim.x + threadIdx.x;
    int v    = gtid >> 5;
    int lane = threadIdx.x & 31;
    if (v >= N_NODES) return;

    int deg = g_deg[v];
    int rs  = g_rowstart[v] + g_bsum[v >> 10];
    int re  = rs + deg;

    float4 a0 = make_float4(0.f, 0.f, 0.f, 0.f);
    float4 a1 = make_float4(0.f, 0.f, 0.f, 0.f);
    float4 a2 = make_float4(0.f, 0.f, 0.f, 0.f);
    float4 a3 = make_float4(0.f, 0.f, 0.f, 0.f);

    int i = rs;
    for (; i + 3 < re; i += 4) {
        int s0 = g_csr[i], s1 = g_csr[i + 1], s2 = g_csr[i + 2], s3 = g_csr[i + 3];
        uint2 u0 = *(const uint2*)(g_h16 + (size_t)s0 * 64 + lane * 2);
        uint2 u1 = *(const uint2*)(g_h16 + (size_t)s1 * 64 + lane * 2);
        uint2 u2 = *(const uint2*)(g_h16 + (size_t)s2 * 64 + lane * 2);
        uint2 u3 = *(const uint2*)(g_h16 + (size_t)s3 * 64 + lane * 2);
        float2 f;
        f = __half22float2(*reinterpret_cast<__half2*>(&u0.x)); a0.x += f.x; a0.y += f.y;
        f = __half22float2(*reinterpret_cast<__half2*>(&u0.y)); a0.z += f.x; a0.w += f.y;
        f = __half22float2(*reinterpret_cast<__half2*>(&u1.x)); a1.x += f.x; a1.y += f.y;
        f = __half22float2(*reinterpret_cast<__half2*>(&u1.y)); a1.z += f.x; a1.w += f.y;
        f = __half22float2(*reinterpret_cast<__half2*>(&u2.x)); a2.x += f.x; a2.y += f.y;
        f = __half22float2(*reinterpret_cast<__half2*>(&u2.y)); a2.z += f.x; a2.w += f.y;
        f = __half22float2(*reinterpret_cast<__half2*>(&u3.x)); a3.x += f.x; a3.y += f.y;
        f = __half22float2(*reinterpret_cast<__half2*>(&u3.y)); a3.z += f.x; a3.w += f.y;
    }
    for (; i < re; i++) {
        int s0 = g_csr[i];
        uint2 u0 = *(const uint2*)(g_h16 + (size_t)s0 * 64 + lane * 2);
        float2 f;
        f = __half22float2(*reinterpret_cast<__half2*>(&u0.x)); a0.x += f.x; a0.y += f.y;
        f = __half22float2(*reinterpret_cast<__half2*>(&u0.y)); a0.z += f.x; a0.w += f.y;
    }

    float inv = 1.0f / (float)max(deg, 1);
    float cx = (a0.x + a1.x + a2.x + a3.x) * inv;
    float cy = (a0.y + a1.y + a2.y + a3.y) * inv;
    float cz = (a0.z + a1.z + a2.z + a3.z) * inv;
    float cw = (a0.w + a1.w + a2.w + a3.w) * inv;
    __half2 p0 = __floats2half2_rn(cx, cy);
    __half2 p1 = __floats2half2_rn(cz, cw);
    uint2 u;
    u.x = *reinterpret_cast<uint32_t*>(&p0);
    u.y = *reinterpret_cast<uint32_t*>(&p1);
    *(uint2*)(g_c16 + (size_t)v * 64 + lane * 2) = u;
}

// ---------------------------------------------------------------------------
// GEMM: h-half (k<128) bf16 3-term; c-half (k>=128) fp16, A single + B hi/lo.
// Block: 256 thr (8 warps), tile M=128 N=128, 4 K-chunks of 64.
// ---------------------------------------------------------------------------
#define SMWB_HI 0
#define SMWB_LO 32768
#define SMWF_HI 65536
#define SMWF_LO 98304
#define SMA_HI  131072
#define SMA_LO  147456
#define SM_BIAS 163840
#define SM_SSQ  164352
#define SM_TOTAL 165376

__global__ void __launch_bounds__(256, 1)
gemm_mma(const float* __restrict__ h,
         const float* __restrict__ bias,
         float* __restrict__ out) {
    extern __shared__ char sm[];
    const uint32_t sb = smem_u32(sm);
    const int tid  = threadIdx.x;
    const int wid  = tid >> 5;
    const int lane = tid & 31;
    const int m0   = blockIdx.x * 128;
    const int mwarp = (wid >> 1) * 32;
    const int nwarp = (wid & 1) * 64;

    if (tid < 128) *(float*)(sm + SM_BIAS + tid * 4) = bias[tid];

    // ---- preload W tiles: bf16 hi/lo (2 chunks) + fp16 hi/lo (2 chunks) ----
    {
        int r = tid >> 1, half = tid & 1;
#pragma unroll
        for (int c = 0; c < 2; c++) {
#pragma unroll
            for (int j = 0; j < 4; j++) {
                uint32_t sw = SW128((uint32_t)(r * 128 + half * 64 + j * 16));
                *(uint4*)(sm + SMWB_HI + c * 16384 + sw) =
                    *(const uint4*)(g_Bhi + r * K2 + c * 64 + half * 32 + j * 8);
                *(uint4*)(sm + SMWB_LO + c * 16384 + sw) =
                    *(const uint4*)(g_Blo + r * K2 + c * 64 + half * 32 + j * 8);
                *(uint4*)(sm + SMWF_HI + c * 16384 + sw) =
                    *(const uint4*)(g_Bfh + r * 128 + c * 64 + half * 32 + j * 8);
                *(uint4*)(sm + SMWF_LO + c * 16384 + sw) =
                    *(const uint4*)(g_Bfl + r * 128 + c * 64 + half * 32 + j * 8);
            }
        }
    }

    const int r = tid >> 1, half = tid & 1;
    int mg = m0 + r;
    if (mg >= N_NODES) mg = N_NODES - 1;

    float acc[2][8][4];
#pragma unroll
    for (int mt = 0; mt < 2; mt++)
#pragma unroll
        for (int nt = 0; nt < 8; nt++)
#pragma unroll
            for (int q = 0; q < 4; q++) acc[mt][nt][q] = 0.0f;

    for (int ch = 0; ch < 4; ch++) {
        if (ch < 2) {
            // ---- A: h fp32 -> bf16 hi/lo, SW128 ----
            const int kb = ch * 64 + half * 32;
#pragma unroll
            for (int j = 0; j < 8; j++) {
                float4 v = *(const float4*)(h + (size_t)mg * D + kb + j * 4);
                __nv_bfloat162 h0 = __float22bfloat162_rn(make_float2(v.x, v.y));
                __nv_bfloat162 h1 = __float22bfloat162_rn(make_float2(v.z, v.w));
                float2 hf0 = __bfloat1622float2(h0);
                float2 hf1 = __bfloat1622float2(h1);
                __nv_bfloat162 l0 = __float22bfloat162_rn(make_float2(v.x - hf0.x, v.y - hf0.y));
                __nv_bfloat162 l1 = __float22bfloat162_rn(make_float2(v.z - hf1.x, v.w - hf1.y));
                unsigned long long hu =
                    (unsigned long long)*reinterpret_cast<uint32_t*>(&h0) |
                    ((unsigned long long)*reinterpret_cast<uint32_t*>(&h1) << 32);
                unsigned long long lu =
                    (unsigned long long)*reinterpret_cast<uint32_t*>(&l0) |
                    ((unsigned long long)*reinterpret_cast<uint32_t*>(&l1) << 32);
                uint32_t sw = SW128((uint32_t)(r * 128 + half * 64 + j * 8));
                *(unsigned long long*)(sm + SMA_HI + sw) = hu;
                *(unsigned long long*)(sm + SMA_LO + sw) = lu;
            }
        } else {
            // ---- A: c fp16 direct, SW128 ----
            const int kb2 = (ch - 2) * 32 + half * 16;   // half2 units
#pragma unroll
            for (int j = 0; j < 4; j++) {
                uint4 v = *(const uint4*)(g_c16 + (size_t)mg * 64 + kb2 + j * 4);
                uint32_t sw = SW128((uint32_t)(r * 128 + half * 64 + j * 16));
                *(uint4*)(sm + SMA_HI + sw) = v;
            }
        }
        __syncthreads();

#pragma unroll
        for (int ks = 0; ks < 4; ks++) {
            const uint32_t kc2 = ks * 32;

            if (ch < 2) {
                uint32_t ah[2][4], al[2][4];
#pragma unroll
                for (int mt = 0; mt < 2; mt++) {
                    uint32_t rowoff = mwarp + mt * 16 + (lane & 7) + ((lane >> 3) & 1) * 8;
                    uint32_t colb   = kc2 + ((lane >> 4) << 4);
                    uint32_t sw = SW128(rowoff * 128 + colb);
                    ldsm_x4(ah[mt], sb + SMA_HI + sw);
                    ldsm_x4(al[mt], sb + SMA_LO + sw);
                }
                uint32_t bh[4][4], bl[4][4];
#pragma unroll
                for (int tp = 0; tp < 4; tp++) {
                    uint32_t j = lane >> 3;
                    uint32_t row = nwarp + tp * 16 + (lane & 7) + ((j >> 1) << 3);
                    uint32_t colb = kc2 + ((j & 1) << 4);
                    uint32_t sw = SW128(row * 128 + colb);
                    ldsm_x4(bh[tp], sb + SMWB_HI + ch * 16384 + sw);
                    ldsm_x4(bl[tp], sb + SMWB_LO + ch * 16384 + sw);
                }
#pragma unroll
                for (int mt = 0; mt < 2; mt++) {
#pragma unroll
                    for (int nt = 0; nt < 8; nt++) {
                        uint32_t b0h = bh[nt >> 1][(nt & 1) * 2 + 0];
                        uint32_t b1h = bh[nt >> 1][(nt & 1) * 2 + 1];
                        uint32_t b0l = bl[nt >> 1][(nt & 1) * 2 + 0];
                        uint32_t b1l = bl[nt >> 1][(nt & 1) * 2 + 1];
                        mma_bf16(acc[mt][nt], ah[mt], b0h, b1h);
                        mma_bf16(acc[mt][nt], ah[mt], b0l, b1l);
                        mma_bf16(acc[mt][nt], al[mt], b0h, b1h);
                    }
                }
            } else {
                uint32_t af[2][4];
#pragma unroll
                for (int mt = 0; mt < 2; mt++) {
                    uint32_t rowoff = mwarp + mt * 16 + (lane & 7) + ((lane >> 3) & 1) * 8;
                    uint32_t colb   = kc2 + ((lane >> 4) << 4);
                    uint32_t sw = SW128(rowoff * 128 + colb);
                    ldsm_x4(af[mt], sb + SMA_HI + sw);
                }
                uint32_t bh[4][4], bl[4][4];
#pragma unroll
                for (int tp = 0; tp < 4; tp++) {
                    uint32_t j = lane >> 3;
                    uint32_t row = nwarp + tp * 16 + (lane & 7) + ((j >> 1) << 3);
                    uint32_t colb = kc2 + ((j & 1) << 4);
                    uint32_t sw = SW128(row * 128 + colb);
                    ldsm_x4(bh[tp], sb + SMWF_HI + (ch - 2) * 16384 + sw);
                    ldsm_x4(bl[tp], sb + SMWF_LO + (ch - 2) * 16384 + sw);
                }
#pragma unroll
                for (int mt = 0; mt < 2; mt++) {
#pragma unroll
                    for (int nt = 0; nt < 8; nt++) {
                        uint32_t b0h = bh[nt >> 1][(nt & 1) * 2 + 0];
                        uint32_t b1h = bh[nt >> 1][(nt & 1) * 2 + 1];
                        uint32_t b0l = bl[nt >> 1][(nt & 1) * 2 + 0];
                        uint32_t b1l = bl[nt >> 1][(nt & 1) * 2 + 1];
                        mma_f16(acc[mt][nt], af[mt], b0h, b1h);
                        mma_f16(acc[mt][nt], af[mt], b0l, b1l);
                    }
                }
            }
        }
        __syncthreads();
    }

    // ---- epilogue: bias -> ssq -> normalize -> relu -> staged store ----
#pragma unroll
    for (int mt = 0; mt < 2; mt++)
#pragma unroll
        for (int nt = 0; nt < 8; nt++) {
            float2 bb = *(const float2*)(sm + SM_BIAS +
                                         (nwarp + nt * 8 + (lane & 3) * 2) * 4);
            acc[mt][nt][0] += bb.x;
            acc[mt][nt][1] += bb.y;
            acc[mt][nt][2] += bb.x;
            acc[mt][nt][3] += bb.y;
        }

    float pp[2][2] = {{0.f, 0.f}, {0.f, 0.f}};
#pragma unroll
    for (int mt = 0; mt < 2; mt++)
#pragma unroll
        for (int nt = 0; nt < 8; nt++) {
            pp[mt][0] += acc[mt][nt][0] * acc[mt][nt][0] +
                         acc[mt][nt][1] * acc[mt][nt][1];
            pp[mt][1] += acc[mt][nt][2] * acc[mt][nt][2] +
                         acc[mt][nt][3] * acc[mt][nt][3];
        }
#pragma unroll
    for (int off = 1; off <= 2; off <<= 1) {
#pragma unroll
        for (int mt = 0; mt < 2; mt++) {
            pp[mt][0] += __shfl_xor_sync(~0u, pp[mt][0], off);
            pp[mt][1] += __shfl_xor_sync(~0u, pp[mt][1], off);
        }
    }
    if ((lane & 3) == 0) {
#pragma unroll
        for (int mt = 0; mt < 2; mt++)
#pragma unroll
            for (int hh = 0; hh < 2; hh++) {
                int row = mwarp + mt * 16 + (lane >> 2) + hh * 8;
                *(float*)(sm + SM_SSQ + (wid & 1) * 512 + row * 4) = pp[mt][hh];
            }
    }
    __syncthreads();

    float sc[2][2];
#pragma unroll
    for (int mt = 0; mt < 2; mt++)
#pragma unroll
        for (int hh = 0; hh < 2; hh++) {
            int row = mwarp + mt * 16 + (lane >> 2) + hh * 8;
            float s = *(const float*)(sm + SM_SSQ + row * 4) +
                      *(const float*)(sm + SM_SSQ + 512 + row * 4);
            sc[mt][hh] = 1.0f / fmaxf(sqrtf(s), 1e-12f);
        }
    __syncthreads();

#pragma unroll
    for (int mt = 0; mt < 2; mt++) {
#pragma unroll
        for (int nt = 0; nt < 8; nt++) {
            int coln = nwarp + nt * 8 + (lane & 3) * 2;
            int row0 = mwarp + mt * 16 + (lane >> 2);
            int row1 = row0 + 8;
            float2 v0, v1;
            v0.x = fmaxf(acc[mt][nt][0] * sc[mt][0], 0.0f);
            v0.y = fmaxf(acc[mt][nt][1] * sc[mt][0], 0.0f);
            v1.x = fmaxf(acc[mt][nt][2] * sc[mt][1], 0.0f);
            v1.y = fmaxf(acc[mt][nt][3] * sc[mt][1], 0.0f);
            *(float2*)(sm + row0 * 512 + ((coln * 4) ^ ((row0 & 7) << 4))) = v0;
            *(float2*)(sm + row1 * 512 + ((coln * 4) ^ ((row1 & 7) << 4))) = v1;
        }
    }
    __syncthreads();

#pragma unroll
    for (int i = 0; i < 16; i++) {
        int idx = tid + i * 256;
        int rr = idx >> 5;
        int p  = idx & 31;
        int mgl = m0 + rr;
        if (mgl < N_NODES) {
            float4 o = *(const float4*)(sm + rr * 512 + ((p * 16) ^ ((rr & 7) << 4)));
            *(float4*)(out + (size_t)mgl * D + p * 4) = o;
        }
    }
}

// ---------------------------------------------------------------------------
extern "C" void kernel_launch(void* const* d_in, const int* in_sizes, int n_in,
                              void* d_out, int out_size) {
    const float* h    = (const float*)d_in[0];
    const float* W    = (const float*)d_in[1];
    const float* bias = (const float*)d_in[2];
    const int*   esrc = (const int*)d_in[3];
    const int*   edst = (const int*)d_in[4];
    float*       out  = (float*)d_out;

    void *p_deg = nullptr, *p_cur = nullptr;
    cudaGetSymbolAddress(&p_deg, g_deg);
    cudaGetSymbolAddress(&p_cur, g_cur);
    cudaMemsetAsync(p_deg, 0, sizeof(int) * N_NODES, 0);
    cudaMemsetAsync(p_cur, 0, sizeof(int) * N_NODES, 0);

    cudaFuncSetAttribute(gemm_mma, cudaFuncAttributeMaxDynamicSharedMemorySize,
                         SM_TOTAL);

    split_W<<<128, 256>>>(W);
    h_to_fp16<<<1600, 256>>>(h);
    hist_deg<<<1184, 256>>>(edst);
    scan_blocks<<<NBLK, 1024>>>();
    scan_top<<<1, 128>>>();
    fill_csr<<<1184, 256>>>(esrc, edst);
    gather_mean16<<<(N_NODES * 32 + 255) / 256, 256>>>();
    gemm_mma<<<(N_NODES + 127) / 128, 256, SM_TOTAL>>>(h, bias, out);
}

// round 8
// speedup vs baseline: 2.2937x; 1.1232x over previous
#include <cuda_runtime.h>
#include <cuda_bf16.h>
#include <cuda_fp16.h>
#include <cstdint>

#define N_NODES 100000
#define N_EDGES 1600000
#define D 128
#define K2 256   // 2*D
#define NBLK 98  // ceil(N_NODES / 1024)

// Scratch (no device mallocs allowed)
__device__ __half2 g_h16[(size_t)N_NODES * (D / 2)];  // fp16 h (25.6 MB)
__device__ __half2 g_c16[(size_t)N_NODES * (D / 2)];  // fp16 c (25.6 MB)
__device__ int   g_deg[N_NODES];
__device__ int   g_rank[N_EDGES];
__device__ int   g_rowstart[N_NODES];
__device__ int   g_bsum[128];
__device__ int   g_csr[N_EDGES];
__device__ __half g_Wfh[D * K2];               // W fp16 hi [n][k], full K
__device__ __half g_Wfl[D * K2];               // W fp16 lo

// ===========================================================================
// Helpers
// ===========================================================================
__device__ __forceinline__ uint32_t smem_u32(const void* p) {
    uint32_t a;
    asm("{ .reg .u64 t; cvta.to.shared.u64 t, %1; cvt.u32.u64 %0, t; }"
        : "=r"(a) : "l"(p));
    return a;
}
#define SW128(o) ((o) ^ (((o) >> 3) & 0x70))

__device__ __forceinline__ void ldsm_x4(uint32_t* r, uint32_t addr) {
    asm volatile("ldmatrix.sync.aligned.m8n8.x4.shared.b16 {%0,%1,%2,%3}, [%4];"
                 : "=r"(r[0]), "=r"(r[1]), "=r"(r[2]), "=r"(r[3]) : "r"(addr));
}
__device__ __forceinline__ void mma_f16(float* c, const uint32_t* a,
                                        uint32_t b0, uint32_t b1) {
    asm volatile(
        "mma.sync.aligned.m16n8k16.row.col.f32.f16.f16.f32 "
        "{%0,%1,%2,%3}, {%4,%5,%6,%7}, {%8,%9}, {%0,%1,%2,%3};"
        : "+f"(c[0]), "+f"(c[1]), "+f"(c[2]), "+f"(c[3])
        : "r"(a[0]), "r"(a[1]), "r"(a[2]), "r"(a[3]), "r"(b0), "r"(b1));
}

// ---------------------------------------------------------------------------
// Prep: blocks 0..127 split W into fp16 hi/lo; blocks 128+ convert h -> fp16.
// ---------------------------------------------------------------------------
__global__ void prep(const float* __restrict__ W, const float* __restrict__ h) {
    int b = blockIdx.x;
    int t = threadIdx.x;
    if (b < 128) {
        int i = b * 256 + t;                       // 0..32767
        float w = W[i];
        __half fh = __float2half(w);
        g_Wfh[i] = fh;
        g_Wfl[i] = __float2half(w - __half2float(fh));
    } else {
        int i = (b - 128) * 256 + t;               // float4 index
        int stride = (gridDim.x - 128) * 256;
        const int total = N_NODES * (D / 4);       // 3.2M
        for (; i < total; i += stride) {
            float4 v = *(const float4*)(h + (size_t)i * 4);
            __half2 a = __floats2half2_rn(v.x, v.y);
            __half2 c = __floats2half2_rn(v.z, v.w);
            uint2 u;
            u.x = *reinterpret_cast<uint32_t*>(&a);
            u.y = *reinterpret_cast<uint32_t*>(&c);
            *(uint2*)(g_h16 + (size_t)i * 2) = u;
        }
    }
}

// ---------------------------------------------------------------------------
// CSR build: histogram (records per-edge rank) -> scans -> rank-based fill
// ---------------------------------------------------------------------------
__global__ void hist_deg(const int* __restrict__ edst) {
    int i = blockIdx.x * blockDim.x + threadIdx.x;
    int stride = gridDim.x * blockDim.x;
    for (int e = i; e < N_EDGES; e += stride)
        g_rank[e] = atomicAdd(&g_deg[edst[e]], 1);
}

__global__ void scan_blocks() {
    __shared__ int wsum[32];
    int t = threadIdx.x, b = blockIdx.x;
    int i = b * 1024 + t;
    int v = (i < N_NODES) ? g_deg[i] : 0;
    int x = v;
#pragma unroll
    for (int o = 1; o < 32; o <<= 1) {
        int y = __shfl_up_sync(~0u, x, o);
        if ((t & 31) >= o) x += y;
    }
    if ((t & 31) == 31) wsum[t >> 5] = x;
    __syncthreads();
    if (t < 32) {
        int s = wsum[t];
#pragma unroll
        for (int o = 1; o < 32; o <<= 1) {
            int y = __shfl_up_sync(~0u, s, o);
            if (t >= o) s += y;
        }
        wsum[t] = s;
    }
    __syncthreads();
    int off = (t >= 32) ? wsum[(t >> 5) - 1] : 0;
    int incl = x + off;
    if (i < N_NODES) g_rowstart[i] = incl - v;
    if (t == 1023) g_bsum[b] = incl;
}

__global__ void scan_top() {
    __shared__ int s[128];
    int t = threadIdx.x;
    int mine = (t < NBLK) ? g_bsum[t] : 0;
    s[t] = mine;
    __syncthreads();
#pragma unroll
    for (int o = 1; o < 128; o <<= 1) {
        int v = (t >= o) ? s[t - o] : 0;
        __syncthreads();
        s[t] += v;
        __syncthreads();
    }
    g_bsum[t] = s[t] - mine;
}

__global__ void fill_csr(const int* __restrict__ esrc,
                         const int* __restrict__ edst) {
    int i = blockIdx.x * blockDim.x + threadIdx.x;
    int stride = gridDim.x * blockDim.x;
    for (int e = i; e < N_EDGES; e += stride) {
        int d = edst[e];
        g_csr[g_rowstart[d] + g_bsum[d >> 10] + g_rank[e]] = esrc[e];
    }
}

// ---------------------------------------------------------------------------
// Segmented gather-mean over fp16 h: one warp per dst node, 4 edges in
// flight, fp32 accumulation, fp16 output row (256B).
// ---------------------------------------------------------------------------
__global__ void __launch_bounds__(256)
gather_mean16() {
    int gtid = blockIdx.x * blockDim.x + threadIdx.x;
    int v    = gtid >> 5;
    int lane = threadIdx.x & 31;
    if (v >= N_NODES) return;

    int deg = g_deg[v];
    int rs  = g_rowstart[v] + g_bsum[v >> 10];
    int re  = rs + deg;

    float4 a0 = make_float4(0.f, 0.f, 0.f, 0.f);
    float4 a1 = make_float4(0.f, 0.f, 0.f, 0.f);
    float4 a2 = make_float4(0.f, 0.f, 0.f, 0.f);
    float4 a3 = make_float4(0.f, 0.f, 0.f, 0.f);

    int i = rs;
    for (; i + 3 < re; i += 4) {
        int s0 = g_csr[i], s1 = g_csr[i + 1], s2 = g_csr[i + 2], s3 = g_csr[i + 3];
        uint2 u0 = *(const uint2*)(g_h16 + (size_t)s0 * 64 + lane * 2);
        uint2 u1 = *(const uint2*)(g_h16 + (size_t)s1 * 64 + lane * 2);
        uint2 u2 = *(const uint2*)(g_h16 + (size_t)s2 * 64 + lane * 2);
        uint2 u3 = *(const uint2*)(g_h16 + (size_t)s3 * 64 + lane * 2);
        float2 f;
        f = __half22float2(*reinterpret_cast<__half2*>(&u0.x)); a0.x += f.x; a0.y += f.y;
        f = __half22float2(*reinterpret_cast<__half2*>(&u0.y)); a0.z += f.x; a0.w += f.y;
        f = __half22float2(*reinterpret_cast<__half2*>(&u1.x)); a1.x += f.x; a1.y += f.y;
        f = __half22float2(*reinterpret_cast<__half2*>(&u1.y)); a1.z += f.x; a1.w += f.y;
        f = __half22float2(*reinterpret_cast<__half2*>(&u2.x)); a2.x += f.x; a2.y += f.y;
        f = __half22float2(*reinterpret_cast<__half2*>(&u2.y)); a2.z += f.x; a2.w += f.y;
        f = __half22float2(*reinterpret_cast<__half2*>(&u3.x)); a3.x += f.x; a3.y += f.y;
        f = __half22float2(*reinterpret_cast<__half2*>(&u3.y)); a3.z += f.x; a3.w += f.y;
    }
    for (; i < re; i++) {
        int s0 = g_csr[i];
        uint2 u0 = *(const uint2*)(g_h16 + (size_t)s0 * 64 + lane * 2);
        float2 f;
        f = __half22float2(*reinterpret_cast<__half2*>(&u0.x)); a0.x += f.x; a0.y += f.y;
        f = __half22float2(*reinterpret_cast<__half2*>(&u0.y)); a0.z += f.x; a0.w += f.y;
    }

    float inv = 1.0f / (float)max(deg, 1);
    float cx = (a0.x + a1.x + a2.x + a3.x) * inv;
    float cy = (a0.y + a1.y + a2.y + a3.y) * inv;
    float cz = (a0.z + a1.z + a2.z + a3.z) * inv;
    float cw = (a0.w + a1.w + a2.w + a3.w) * inv;
    __half2 p0 = __floats2half2_rn(cx, cy);
    __half2 p1 = __floats2half2_rn(cz, cw);
    uint2 u;
    u.x = *reinterpret_cast<uint32_t*>(&p0);
    u.y = *reinterpret_cast<uint32_t*>(&p1);
    *(uint2*)(g_c16 + (size_t)v * 64 + lane * 2) = u;
}

// ---------------------------------------------------------------------------
// Uniform fp16 GEMM: A single-term fp16 (from g_h16 / g_c16), B 2-term fp16.
// Block: 256 thr (8 warps), tile M=128 N=128, 4 K-chunks of 64.
// ---------------------------------------------------------------------------
#define SMW_HI  0         // 4 chunks x 16KB = 65536
#define SMW_LO  65536
#define SMA     131072    // 16KB
#define SM_BIAS 147456
#define SM_SSQ  147968
#define SM_TOTAL 148992

__global__ void __launch_bounds__(256, 1)
gemm_mma(const float* __restrict__ bias, float* __restrict__ out) {
    extern __shared__ char sm[];
    const uint32_t sb = smem_u32(sm);
    const int tid  = threadIdx.x;
    const int wid  = tid >> 5;
    const int lane = tid & 31;
    const int m0   = blockIdx.x * 128;
    const int mwarp = (wid >> 1) * 32;
    const int nwarp = (wid & 1) * 64;

    if (tid < 128) *(float*)(sm + SM_BIAS + tid * 4) = bias[tid];

    // ---- preload W fp16 hi/lo (4 chunks, SW128) ----
    {
        int r = tid >> 1, half = tid & 1;
#pragma unroll
        for (int c = 0; c < 4; c++) {
#pragma unroll
            for (int j = 0; j < 4; j++) {
                uint32_t sw = SW128((uint32_t)(r * 128 + half * 64 + j * 16));
                *(uint4*)(sm + SMW_HI + c * 16384 + sw) =
                    *(const uint4*)(g_Wfh + r * K2 + c * 64 + half * 32 + j * 8);
                *(uint4*)(sm + SMW_LO + c * 16384 + sw) =
                    *(const uint4*)(g_Wfl + r * K2 + c * 64 + half * 32 + j * 8);
            }
        }
    }

    const int r = tid >> 1, half = tid & 1;
    int mg = m0 + r;
    if (mg >= N_NODES) mg = N_NODES - 1;

    float acc[2][8][4];
#pragma unroll
    for (int mt = 0; mt < 2; mt++)
#pragma unroll
        for (int nt = 0; nt < 8; nt++)
#pragma unroll
            for (int q = 0; q < 4; q++) acc[mt][nt][q] = 0.0f;

    for (int ch = 0; ch < 4; ch++) {
        // ---- A chunk: fp16 direct copy, SW128 ----
        const __half2* asrc = ((ch < 2) ? g_h16 : g_c16) +
                              (size_t)mg * 64 + (ch & 1) * 32 + half * 16;
#pragma unroll
        for (int j = 0; j < 4; j++) {
            uint4 v = *(const uint4*)(asrc + j * 4);
            uint32_t sw = SW128((uint32_t)(r * 128 + half * 64 + j * 16));
            *(uint4*)(sm + SMA + sw) = v;
        }
        __syncthreads();

#pragma unroll
        for (int ks = 0; ks < 4; ks++) {
            const uint32_t kc2 = ks * 32;

            uint32_t af[2][4];
#pragma unroll
            for (int mt = 0; mt < 2; mt++) {
                uint32_t rowoff = mwarp + mt * 16 + (lane & 7) + ((lane >> 3) & 1) * 8;
                uint32_t colb   = kc2 + ((lane >> 4) << 4);
                uint32_t sw = SW128(rowoff * 128 + colb);
                ldsm_x4(af[mt], sb + SMA + sw);
            }
            uint32_t bh[4][4], bl[4][4];
#pragma unroll
            for (int tp = 0; tp < 4; tp++) {
                uint32_t j = lane >> 3;
                uint32_t row = nwarp + tp * 16 + (lane & 7) + ((j >> 1) << 3);
                uint32_t colb = kc2 + ((j & 1) << 4);
                uint32_t sw = SW128(row * 128 + colb);
                ldsm_x4(bh[tp], sb + SMW_HI + ch * 16384 + sw);
                ldsm_x4(bl[tp], sb + SMW_LO + ch * 16384 + sw);
            }
#pragma unroll
            for (int mt = 0; mt < 2; mt++) {
#pragma unroll
                for (int nt = 0; nt < 8; nt++) {
                    uint32_t b0h = bh[nt >> 1][(nt & 1) * 2 + 0];
                    uint32_t b1h = bh[nt >> 1][(nt & 1) * 2 + 1];
                    uint32_t b0l = bl[nt >> 1][(nt & 1) * 2 + 0];
                    uint32_t b1l = bl[nt >> 1][(nt & 1) * 2 + 1];
                    mma_f16(acc[mt][nt], af[mt], b0h, b1h);
                    mma_f16(acc[mt][nt], af[mt], b0l, b1l);
                }
            }
        }
        __syncthreads();
    }

    // ---- epilogue: bias -> ssq -> normalize -> relu -> staged store ----
#pragma unroll
    for (int mt = 0; mt < 2; mt++)
#pragma unroll
        for (int nt = 0; nt < 8; nt++) {
            float2 bb = *(const float2*)(sm + SM_BIAS +
                                         (nwarp + nt * 8 + (lane & 3) * 2) * 4);
            acc[mt][nt][0] += bb.x;
            acc[mt][nt][1] += bb.y;
            acc[mt][nt][2] += bb.x;
            acc[mt][nt][3] += bb.y;
        }

    float pp[2][2] = {{0.f, 0.f}, {0.f, 0.f}};
#pragma unroll
    for (int mt = 0; mt < 2; mt++)
#pragma unroll
        for (int nt = 0; nt < 8; nt++) {
            pp[mt][0] += acc[mt][nt][0] * acc[mt][nt][0] +
                         acc[mt][nt][1] * acc[mt][nt][1];
            pp[mt][1] += acc[mt][nt][2] * acc[mt][nt][2] +
                         acc[mt][nt][3] * acc[mt][nt][3];
        }
#pragma unroll
    for (int off = 1; off <= 2; off <<= 1) {
#pragma unroll
        for (int mt = 0; mt < 2; mt++) {
            pp[mt][0] += __shfl_xor_sync(~0u, pp[mt][0], off);
            pp[mt][1] += __shfl_xor_sync(~0u, pp[mt][1], off);
        }
    }
    if ((lane & 3) == 0) {
#pragma unroll
        for (int mt = 0; mt < 2; mt++)
#pragma unroll
            for (int hh = 0; hh < 2; hh++) {
                int row = mwarp + mt * 16 + (lane >> 2) + hh * 8;
                *(float*)(sm + SM_SSQ + (wid & 1) * 512 + row * 4) = pp[mt][hh];
            }
    }
    __syncthreads();

    float sc[2][2];
#pragma unroll
    for (int mt = 0; mt < 2; mt++)
#pragma unroll
        for (int hh = 0; hh < 2; hh++) {
            int row = mwarp + mt * 16 + (lane >> 2) + hh * 8;
            float s = *(const float*)(sm + SM_SSQ + row * 4) +
                      *(const float*)(sm + SM_SSQ + 512 + row * 4);
            sc[mt][hh] = 1.0f / fmaxf(sqrtf(s), 1e-12f);
        }
    __syncthreads();

    // stage relu'd rows into SMEM (reuse W region) then coalesced store
#pragma unroll
    for (int mt = 0; mt < 2; mt++) {
#pragma unroll
        for (int nt = 0; nt < 8; nt++) {
            int coln = nwarp + nt * 8 + (lane & 3) * 2;
            int row0 = mwarp + mt * 16 + (lane >> 2);
            int row1 = row0 + 8;
            float2 v0, v1;
            v0.x = fmaxf(acc[mt][nt][0] * sc[mt][0], 0.0f);
            v0.y = fmaxf(acc[mt][nt][1] * sc[mt][0], 0.0f);
            v1.x = fmaxf(acc[mt][nt][2] * sc[mt][1], 0.0f);
            v1.y = fmaxf(acc[mt][nt][3] * sc[mt][1], 0.0f);
            *(float2*)(sm + row0 * 512 + ((coln * 4) ^ ((row0 & 7) << 4))) = v0;
            *(float2*)(sm + row1 * 512 + ((coln * 4) ^ ((row1 & 7) << 4))) = v1;
        }
    }
    __syncthreads();

#pragma unroll
    for (int i = 0; i < 16; i++) {
        int idx = tid + i * 256;
        int rr = idx >> 5;
        int p  = idx & 31;
        int mgl = m0 + rr;
        if (mgl < N_NODES) {
            float4 o = *(const float4*)(sm + rr * 512 + ((p * 16) ^ ((rr & 7) << 4)));
            *(float4*)(out + (size_t)mgl * D + p * 4) = o;
        }
    }
}

// ---------------------------------------------------------------------------
extern "C" void kernel_launch(void* const* d_in, const int* in_sizes, int n_in,
                              void* d_out, int out_size) {
    const float* h    = (const float*)d_in[0];
    const float* W    = (const float*)d_in[1];
    const float* bias = (const float*)d_in[2];
    const int*   esrc = (const int*)d_in[3];
    const int*   edst = (const int*)d_in[4];
    float*       out  = (float*)d_out;

    void* p_deg = nullptr;
    cudaGetSymbolAddress(&p_deg, g_deg);
    cudaMemsetAsync(p_deg, 0, sizeof(int) * N_NODES, 0);

    cudaFuncSetAttribute(gemm_mma, cudaFuncAttributeMaxDynamicSharedMemorySize,
                         SM_TOTAL);

    prep<<<1728, 256>>>(W, h);
    hist_deg<<<1184, 256>>>(edst);
    scan_blocks<<<NBLK, 1024>>>();
    scan_top<<<1, 128>>>();
    fill_csr<<<1184, 256>>>(esrc, edst);
    gather_mean16<<<(N_NODES * 32 + 255) / 256, 256>>>();
    gemm_mma<<<(N_NODES + 127) / 128, 256, SM_TOTAL>>>(bias, out);
}

// round 9
// speedup vs baseline: 2.9865x; 1.3020x over previous
#include <cuda_runtime.h>
#include <cuda_bf16.h>
#include <cuda_fp16.h>
#include <cstdint>

#define N_NODES 100000
#define N_EDGES 1600000
#define D 128
#define K2 256   // 2*D
#define NBLK 98  // ceil(N_NODES / 1024)
#define E4 (N_EDGES / 4)   // 400000

// Scratch (no device mallocs allowed)
__device__ __half2 g_h16[(size_t)N_NODES * (D / 2)];  // fp16 h (25.6 MB)
__device__ __half2 g_c16[(size_t)N_NODES * (D / 2)];  // fp16 c (25.6 MB)
__device__ int   g_deg[N_NODES];
__device__ int   g_rank[N_EDGES];
__device__ int   g_rowstart[N_NODES];
__device__ int   g_bsum[128];
__device__ int   g_csr[N_EDGES];
__device__ __half g_Wf[D * K2];                // W fp16 [n][k], full K

// ===========================================================================
// Helpers
// ===========================================================================
__device__ __forceinline__ uint32_t smem_u32(const void* p) {
    uint32_t a;
    asm("{ .reg .u64 t; cvta.to.shared.u64 t, %1; cvt.u32.u64 %0, t; }"
        : "=r"(a) : "l"(p));
    return a;
}
#define SW128(o) ((o) ^ (((o) >> 3) & 0x70))

__device__ __forceinline__ void ldsm_x4(uint32_t* r, uint32_t addr) {
    asm volatile("ldmatrix.sync.aligned.m8n8.x4.shared.b16 {%0,%1,%2,%3}, [%4];"
                 : "=r"(r[0]), "=r"(r[1]), "=r"(r[2]), "=r"(r[3]) : "r"(addr));
}
__device__ __forceinline__ void mma_f16(float* c, const uint32_t* a,
                                        uint32_t b0, uint32_t b1) {
    asm volatile(
        "mma.sync.aligned.m16n8k16.row.col.f32.f16.f16.f32 "
        "{%0,%1,%2,%3}, {%4,%5,%6,%7}, {%8,%9}, {%0,%1,%2,%3};"
        : "+f"(c[0]), "+f"(c[1]), "+f"(c[2]), "+f"(c[3])
        : "r"(a[0]), "r"(a[1]), "r"(a[2]), "r"(a[3]), "r"(b0), "r"(b1));
}

// ---------------------------------------------------------------------------
// Fused prep + histogram. Block ranges:
//   [0,128)      : W -> fp16
//   [128,1728)   : h -> fp16
//   [1728,3291)  : edge histogram (4 edges/thread, int4) + rank record
// ---------------------------------------------------------------------------
__global__ void prep_hist(const float* __restrict__ W,
                          const float* __restrict__ h,
                          const int* __restrict__ edst) {
    int b = blockIdx.x;
    int t = threadIdx.x;
    if (b < 128) {
        int i = b * 256 + t;                       // 0..32767
        g_Wf[i] = __float2half(W[i]);
    } else if (b < 1728) {
        int i = (b - 128) * 256 + t;               // float4 index
        int stride = 1600 * 256;
        const int total = N_NODES * (D / 4);       // 3.2M
        for (; i < total; i += stride) {
            float4 v = *(const float4*)(h + (size_t)i * 4);
            __half2 a = __floats2half2_rn(v.x, v.y);
            __half2 c = __floats2half2_rn(v.z, v.w);
            uint2 u;
            u.x = *reinterpret_cast<uint32_t*>(&a);
            u.y = *reinterpret_cast<uint32_t*>(&c);
            *(uint2*)(g_h16 + (size_t)i * 2) = u;
        }
    } else {
        int gi = (b - 1728) * 256 + t;             // int4 edge-group index
        if (gi < E4) {
            int4 d4 = ((const int4*)edst)[gi];
            int4 r4;
            r4.x = atomicAdd(&g_deg[d4.x], 1);
            r4.y = atomicAdd(&g_deg[d4.y], 1);
            r4.z = atomicAdd(&g_deg[d4.z], 1);
            r4.w = atomicAdd(&g_deg[d4.w], 1);
            ((int4*)g_rank)[gi] = r4;
        }
    }
}

// ---------------------------------------------------------------------------
// Scans
// ---------------------------------------------------------------------------
__global__ void scan_blocks() {
    __shared__ int wsum[32];
    int t = threadIdx.x, b = blockIdx.x;
    int i = b * 1024 + t;
    int v = (i < N_NODES) ? g_deg[i] : 0;
    int x = v;
#pragma unroll
    for (int o = 1; o < 32; o <<= 1) {
        int y = __shfl_up_sync(~0u, x, o);
        if ((t & 31) >= o) x += y;
    }
    if ((t & 31) == 31) wsum[t >> 5] = x;
    __syncthreads();
    if (t < 32) {
        int s = wsum[t];
#pragma unroll
        for (int o = 1; o < 32; o <<= 1) {
            int y = __shfl_up_sync(~0u, s, o);
            if (t >= o) s += y;
        }
        wsum[t] = s;
    }
    __syncthreads();
    int off = (t >= 32) ? wsum[(t >> 5) - 1] : 0;
    int incl = x + off;
    if (i < N_NODES) g_rowstart[i] = incl - v;
    if (t == 1023) g_bsum[b] = incl;
}

__global__ void scan_top() {
    __shared__ int s[128];
    int t = threadIdx.x;
    int mine = (t < NBLK) ? g_bsum[t] : 0;
    s[t] = mine;
    __syncthreads();
#pragma unroll
    for (int o = 1; o < 128; o <<= 1) {
        int v = (t >= o) ? s[t - o] : 0;
        __syncthreads();
        s[t] += v;
        __syncthreads();
    }
    g_bsum[t] = s[t] - mine;
}

// ---------------------------------------------------------------------------
// Atomic-free CSR fill: 4 edges/thread, int4 loads.
// ---------------------------------------------------------------------------
__global__ void fill_csr(const int* __restrict__ esrc,
                         const int* __restrict__ edst) {
    int gi = blockIdx.x * blockDim.x + threadIdx.x;
    if (gi >= E4) return;
    int4 d4 = ((const int4*)edst)[gi];
    int4 s4 = ((const int4*)esrc)[gi];
    int4 r4 = ((const int4*)g_rank)[gi];
    g_csr[g_rowstart[d4.x] + g_bsum[d4.x >> 10] + r4.x] = s4.x;
    g_csr[g_rowstart[d4.y] + g_bsum[d4.y >> 10] + r4.y] = s4.y;
    g_csr[g_rowstart[d4.z] + g_bsum[d4.z >> 10] + r4.z] = s4.z;
    g_csr[g_rowstart[d4.w] + g_bsum[d4.w >> 10] + r4.w] = s4.w;
}

// ---------------------------------------------------------------------------
// Segmented gather-mean over fp16 h: one warp per dst node, 4 edges in
// flight, fp32 accumulation, fp16 output row (256B).
// ---------------------------------------------------------------------------
__global__ void __launch_bounds__(256)
gather_mean16() {
    int gtid = blockIdx.x * blockDim.x + threadIdx.x;
    int v    = gtid >> 5;
    int lane = threadIdx.x & 31;
    if (v >= N_NODES) return;

    int deg = g_deg[v];
    int rs  = g_rowstart[v] + g_bsum[v >> 10];
    int re  = rs + deg;

    float4 a0 = make_float4(0.f, 0.f, 0.f, 0.f);
    float4 a1 = make_float4(0.f, 0.f, 0.f, 0.f);
    float4 a2 = make_float4(0.f, 0.f, 0.f, 0.f);
    float4 a3 = make_float4(0.f, 0.f, 0.f, 0.f);

    int i = rs;
    for (; i + 3 < re; i += 4) {
        int s0 = g_csr[i], s1 = g_csr[i + 1], s2 = g_csr[i + 2], s3 = g_csr[i + 3];
        uint2 u0 = *(const uint2*)(g_h16 + (size_t)s0 * 64 + lane * 2);
        uint2 u1 = *(const uint2*)(g_h16 + (size_t)s1 * 64 + lane * 2);
        uint2 u2 = *(const uint2*)(g_h16 + (size_t)s2 * 64 + lane * 2);
        uint2 u3 = *(const uint2*)(g_h16 + (size_t)s3 * 64 + lane * 2);
        float2 f;
        f = __half22float2(*reinterpret_cast<__half2*>(&u0.x)); a0.x += f.x; a0.y += f.y;
        f = __half22float2(*reinterpret_cast<__half2*>(&u0.y)); a0.z += f.x; a0.w += f.y;
        f = __half22float2(*reinterpret_cast<__half2*>(&u1.x)); a1.x += f.x; a1.y += f.y;
        f = __half22float2(*reinterpret_cast<__half2*>(&u1.y)); a1.z += f.x; a1.w += f.y;
        f = __half22float2(*reinterpret_cast<__half2*>(&u2.x)); a2.x += f.x; a2.y += f.y;
        f = __half22float2(*reinterpret_cast<__half2*>(&u2.y)); a2.z += f.x; a2.w += f.y;
        f = __half22float2(*reinterpret_cast<__half2*>(&u3.x)); a3.x += f.x; a3.y += f.y;
        f = __half22float2(*reinterpret_cast<__half2*>(&u3.y)); a3.z += f.x; a3.w += f.y;
    }
    for (; i < re; i++) {
        int s0 = g_csr[i];
        uint2 u0 = *(const uint2*)(g_h16 + (size_t)s0 * 64 + lane * 2);
        float2 f;
        f = __half22float2(*reinterpret_cast<__half2*>(&u0.x)); a0.x += f.x; a0.y += f.y;
        f = __half22float2(*reinterpret_cast<__half2*>(&u0.y)); a0.z += f.x; a0.w += f.y;
    }

    float inv = 1.0f / (float)max(deg, 1);
    float cx = (a0.x + a1.x + a2.x + a3.x) * inv;
    float cy = (a0.y + a1.y + a2.y + a3.y) * inv;
    float cz = (a0.z + a1.z + a2.z + a3.z) * inv;
    float cw = (a0.w + a1.w + a2.w + a3.w) * inv;
    __half2 p0 = __floats2half2_rn(cx, cy);
    __half2 p1 = __floats2half2_rn(cz, cw);
    uint2 u;
    u.x = *reinterpret_cast<uint32_t*>(&p0);
    u.y = *reinterpret_cast<uint32_t*>(&p1);
    *(uint2*)(g_c16 + (size_t)v * 64 + lane * 2) = u;
}

// ---------------------------------------------------------------------------
// fp16 GEMM, single-term A and W. Block: 256 thr (8 warps), tile M=128 N=128,
// 4 K-chunks of 64. 2 blocks/SM.
// ---------------------------------------------------------------------------
#define SMW     0         // 4 chunks x 16KB = 65536 (reused for output stage)
#define SMA     65536     // 16KB
#define SM_BIAS 81920
#define SM_SSQ  82432
#define SM_TOTAL 83456

__global__ void __launch_bounds__(256, 2)
gemm_mma(const float* __restrict__ bias, float* __restrict__ out) {
    extern __shared__ char sm[];
    const uint32_t sb = smem_u32(sm);
    const int tid  = threadIdx.x;
    const int wid  = tid >> 5;
    const int lane = tid & 31;
    const int m0   = blockIdx.x * 128;
    const int mwarp = (wid >> 1) * 32;
    const int nwarp = (wid & 1) * 64;

    if (tid < 128) *(float*)(sm + SM_BIAS + tid * 4) = bias[tid];

    // ---- preload W fp16 (4 chunks, SW128) ----
    {
        int r = tid >> 1, half = tid & 1;
#pragma unroll
        for (int c = 0; c < 4; c++) {
#pragma unroll
            for (int j = 0; j < 4; j++) {
                uint32_t sw = SW128((uint32_t)(r * 128 + half * 64 + j * 16));
                *(uint4*)(sm + SMW + c * 16384 + sw) =
                    *(const uint4*)(g_Wf + r * K2 + c * 64 + half * 32 + j * 8);
            }
        }
    }

    const int r = tid >> 1, half = tid & 1;
    int mg = m0 + r;
    if (mg >= N_NODES) mg = N_NODES - 1;

    float acc[2][8][4];
#pragma unroll
    for (int mt = 0; mt < 2; mt++)
#pragma unroll
        for (int nt = 0; nt < 8; nt++)
#pragma unroll
            for (int q = 0; q < 4; q++) acc[mt][nt][q] = 0.0f;

    for (int ch = 0; ch < 4; ch++) {
        // ---- A chunk: fp16 direct copy, SW128 ----
        const __half2* asrc = ((ch < 2) ? g_h16 : g_c16) +
                              (size_t)mg * 64 + (ch & 1) * 32 + half * 16;
#pragma unroll
        for (int j = 0; j < 4; j++) {
            uint4 v = *(const uint4*)(asrc + j * 4);
            uint32_t sw = SW128((uint32_t)(r * 128 + half * 64 + j * 16));
            *(uint4*)(sm + SMA + sw) = v;
        }
        __syncthreads();

#pragma unroll
        for (int ks = 0; ks < 4; ks++) {
            const uint32_t kc2 = ks * 32;

            uint32_t af[2][4];
#pragma unroll
            for (int mt = 0; mt < 2; mt++) {
                uint32_t rowoff = mwarp + mt * 16 + (lane & 7) + ((lane >> 3) & 1) * 8;
                uint32_t colb   = kc2 + ((lane >> 4) << 4);
                uint32_t sw = SW128(rowoff * 128 + colb);
                ldsm_x4(af[mt], sb + SMA + sw);
            }
            uint32_t bw[4][4];
#pragma unroll
            for (int tp = 0; tp < 4; tp++) {
                uint32_t j = lane >> 3;
                uint32_t row = nwarp + tp * 16 + (lane & 7) + ((j >> 1) << 3);
                uint32_t colb = kc2 + ((j & 1) << 4);
                uint32_t sw = SW128(row * 128 + colb);
                ldsm_x4(bw[tp], sb + SMW + ch * 16384 + sw);
            }
#pragma unroll
            for (int mt = 0; mt < 2; mt++) {
#pragma unroll
                for (int nt = 0; nt < 8; nt++) {
                    uint32_t b0 = bw[nt >> 1][(nt & 1) * 2 + 0];
                    uint32_t b1 = bw[nt >> 1][(nt & 1) * 2 + 1];
                    mma_f16(acc[mt][nt], af[mt], b0, b1);
                }
            }
        }
        __syncthreads();
    }

    // ---- epilogue: bias -> ssq -> normalize -> relu -> staged store ----
#pragma unroll
    for (int mt = 0; mt < 2; mt++)
#pragma unroll
        for (int nt = 0; nt < 8; nt++) {
            float2 bb = *(const float2*)(sm + SM_BIAS +
                                         (nwarp + nt * 8 + (lane & 3) * 2) * 4);
            acc[mt][nt][0] += bb.x;
            acc[mt][nt][1] += bb.y;
            acc[mt][nt][2] += bb.x;
            acc[mt][nt][3] += bb.y;
        }

    float pp[2][2] = {{0.f, 0.f}, {0.f, 0.f}};
#pragma unroll
    for (int mt = 0; mt < 2; mt++)
#pragma unroll
        for (int nt = 0; nt < 8; nt++) {
            pp[mt][0] += acc[mt][nt][0] * acc[mt][nt][0] +
                         acc[mt][nt][1] * acc[mt][nt][1];
            pp[mt][1] += acc[mt][nt][2] * acc[mt][nt][2] +
                         acc[mt][nt][3] * acc[mt][nt][3];
        }
#pragma unroll
    for (int off = 1; off <= 2; off <<= 1) {
#pragma unroll
        for (int mt = 0; mt < 2; mt++) {
            pp[mt][0] += __shfl_xor_sync(~0u, pp[mt][0], off);
            pp[mt][1] += __shfl_xor_sync(~0u, pp[mt][1], off);
        }
    }
    if ((lane & 3) == 0) {
#pragma unroll
        for (int mt = 0; mt < 2; mt++)
#pragma unroll
            for (int hh = 0; hh < 2; hh++) {
                int row = mwarp + mt * 16 + (lane >> 2) + hh * 8;
                *(float*)(sm + SM_SSQ + (wid & 1) * 512 + row * 4) = pp[mt][hh];
            }
    }
    __syncthreads();

    float sc[2][2];
#pragma unroll
    for (int mt = 0; mt < 2; mt++)
#pragma unroll
        for (int hh = 0; hh < 2; hh++) {
            int row = mwarp + mt * 16 + (lane >> 2) + hh * 8;
            float s = *(const float*)(sm + SM_SSQ + row * 4) +
                      *(const float*)(sm + SM_SSQ + 512 + row * 4);
            sc[mt][hh] = 1.0f / fmaxf(sqrtf(s), 1e-12f);
        }
    __syncthreads();

    // stage relu'd rows into SMEM (reuse W region) then coalesced store
#pragma unroll
    for (int mt = 0; mt < 2; mt++) {
#pragma unroll
        for (int nt = 0; nt < 8; nt++) {
            int coln = nwarp + nt * 8 + (lane & 3) * 2;
            int row0 = mwarp + mt * 16 + (lane >> 2);
            int row1 = row0 + 8;
            float2 v0, v1;
            v0.x = fmaxf(acc[mt][nt][0] * sc[mt][0], 0.0f);
            v0.y = fmaxf(acc[mt][nt][1] * sc[mt][0], 0.0f);
            v1.x = fmaxf(acc[mt][nt][2] * sc[mt][1], 0.0f);
            v1.y = fmaxf(acc[mt][nt][3] * sc[mt][1], 0.0f);
            *(float2*)(sm + row0 * 512 + ((coln * 4) ^ ((row0 & 7) << 4))) = v0;
            *(float2*)(sm + row1 * 512 + ((coln * 4) ^ ((row1 & 7) << 4))) = v1;
        }
    }
    __syncthreads();

#pragma unroll
    for (int i = 0; i < 16; i++) {
        int idx = tid + i * 256;
        int rr = idx >> 5;
        int p  = idx & 31;
        int mgl = m0 + rr;
        if (mgl < N_NODES) {
            float4 o = *(const float4*)(sm + rr * 512 + ((p * 16) ^ ((rr & 7) << 4)));
            *(float4*)(out + (size_t)mgl * D + p * 4) = o;
        }
    }
}

// ---------------------------------------------------------------------------
extern "C" void kernel_launch(void* const* d_in, const int* in_sizes, int n_in,
                              void* d_out, int out_size) {
    const float* h    = (const float*)d_in[0];
    const float* W    = (const float*)d_in[1];
    const float* bias = (const float*)d_in[2];
    const int*   esrc = (const int*)d_in[3];
    const int*   edst = (const int*)d_in[4];
    float*       out  = (float*)d_out;

    void* p_deg = nullptr;
    cudaGetSymbolAddress(&p_deg, g_deg);
    cudaMemsetAsync(p_deg, 0, sizeof(int) * N_NODES, 0);

    cudaFuncSetAttribute(gemm_mma, cudaFuncAttributeMaxDynamicSharedMemorySize,
                         SM_TOTAL);

    prep_hist<<<1728 + (E4 + 255) / 256, 256>>>(W, h, edst);
    scan_blocks<<<NBLK, 1024>>>();
    scan_top<<<1, 128>>>();
    fill_csr<<<(E4 + 255) / 256, 256>>>(esrc, edst);
    gather_mean16<<<(N_NODES * 32 + 255) / 256, 256>>>();
    gemm_mma<<<(N_NODES + 127) / 128, 256, SM_TOTAL>>>(bias, out);
}